// round 7
// baseline (speedup 1.0000x reference)
#include <cuda_runtime.h>
#include <cuda_bf16.h>
#include <cstdint>

// Problem constants (fixed by the dataset)
constexpr int U_N  = 50000;
constexpr int I_N  = 100000;
constexpr int N_N  = 150000;   // U + I
constexpr int D    = 64;
constexpr int B_N  = 8192;
constexpr int HID  = 128;

constexpr int NTOT  = N_N + 2 * U_N + 2 * I_N;   // 450000 CSR rows (5 graphs)
constexpr int NSCAN = NTOT + 1;
constexpr int E_TOT = 5000000;

// int scratch layout
constexpr int OFF_DEG  = 0;
constexpr int DEG_PAD  = 450008;
constexpr int OFF_CNT  = DEG_PAD;
constexpr int CNT_PAD  = 450008;
constexpr int OFF_DOUT = OFF_CNT + CNT_PAD;
constexpr int DOUT_LEN = 2 * U_N + 2 * I_N;      // 300000
constexpr int OFF_PART = OFF_DOUT + DOUT_LEN;
constexpr int INT_TOT  = OFF_PART + 256;

// CSR row bases within the concatenated degree/scan vector
constexpr int RB_GCN = 0;
constexpr int RB_U1  = N_N;
constexpr int RB_U2  = N_N + U_N;
constexpr int RB_I1  = N_N + 2 * U_N;
constexpr int RB_I2  = N_N + 2 * U_N + I_N;

// ---------------------------------------------------------------------------
// Scratch (device globals: allocation-free)
// ---------------------------------------------------------------------------
__device__ __align__(256) float g_ui_a[N_N * D];
__device__ __align__(256) float g_ui_b[N_N * D];
__device__ __align__(256) float g_hu[U_N * D];
__device__ __align__(256) float g_hi[I_N * D];
__device__ __align__(256) float g_zu[U_N * 2 * D];
__device__ __align__(256) float g_zi[I_N * 2 * D];
__device__ __align__(256) float g_wdst[NTOT];
__device__ __align__(256) float g_wsrc[DOUT_LEN];
__device__ __align__(256) float g_wsum[4];
__device__ __align__(256) float g_beta[4];
__device__ __align__(256) int   g_int[INT_TOT];
__device__ __align__(256) int   g_S[NSCAN + 8];
__device__ __align__(256) int   g_csr[E_TOT];

// ---------------------------------------------------------------------------
// Helpers
// ---------------------------------------------------------------------------
__device__ __forceinline__ float tanh_fast(float x) {
    float y;
    asm("tanh.approx.f32 %0, %1;" : "=f"(y) : "f"(x));
    return y;
}
__device__ __forceinline__ uint32_t pack_bf16(float lo, float hi) {
    uint32_t r;
    asm("cvt.rn.bf16x2.f32 %0, %1, %2;" : "=r"(r) : "f"(hi), "f"(lo));
    return r;
}
__device__ __forceinline__ void mma16816(float c[4], const uint32_t a[4],
                                         uint32_t b0, uint32_t b1) {
    asm volatile(
        "mma.sync.aligned.m16n8k16.row.col.f32.bf16.bf16.f32 "
        "{%0,%1,%2,%3}, {%4,%5,%6,%7}, {%8,%9}, {%0,%1,%2,%3};"
        : "+f"(c[0]), "+f"(c[1]), "+f"(c[2]), "+f"(c[3])
        : "r"(a[0]), "r"(a[1]), "r"(a[2]), "r"(a[3]), "r"(b0), "r"(b1));
}

// ---------------------------------------------------------------------------
// Kernels
// ---------------------------------------------------------------------------
__global__ void zero_i4_k(int4* p, int n4) {
    int t = blockIdx.x * blockDim.x + threadIdx.x;
    if (t < n4) p[t] = make_int4(0, 0, 0, 0);
}

__global__ void init_k(const float4* __restrict__ uf, const float4* __restrict__ itf,
                       float4* __restrict__ ui, float4* __restrict__ hu,
                       float4* __restrict__ hi) {
    int t = blockIdx.x * blockDim.x + threadIdx.x;
    if (t >= N_N * 16) return;
    if (t < U_N * 16) {
        float4 v = uf[t];
        ui[t] = v; hu[t] = v;
    } else {
        float4 v = itf[t - U_N * 16];
        ui[t] = v; hi[t - U_N * 16] = v;
    }
}

__global__ void cnt_k(const int* __restrict__ idx, int E, int* __restrict__ deg) {
    int t = blockIdx.x * blockDim.x + threadIdx.x;
    if (t < E) atomicAdd(&deg[idx[t]], 1);
}

// --- 3-phase exclusive scan over NSCAN ints (chunk = 2048) ---
__global__ void scan1_k(const int* __restrict__ deg, int n,
                        int* __restrict__ S, int* __restrict__ part) {
    __shared__ int warpsum[8];
    int base = blockIdx.x * 2048 + threadIdx.x * 8;
    int v[8];
    int s = 0;
    #pragma unroll
    for (int i = 0; i < 8; i++) {
        int x = (base + i < n) ? deg[base + i] : 0;
        v[i] = s; s += x;
    }
    int lane = threadIdx.x & 31, w = threadIdx.x >> 5;
    int ts = s;
    #pragma unroll
    for (int o = 1; o < 32; o <<= 1) {
        int y = __shfl_up_sync(0xffffffffu, ts, o);
        if (lane >= o) ts += y;
    }
    if (lane == 31) warpsum[w] = ts;
    __syncthreads();
    if (w == 0 && lane < 8) {
        int x = warpsum[lane];
        #pragma unroll
        for (int o = 1; o < 8; o <<= 1) {
            int y = __shfl_up_sync(0xffu, x, o);
            if (lane >= o) x += y;
        }
        warpsum[lane] = x;
    }
    __syncthreads();
    int prefix = (w > 0 ? warpsum[w - 1] : 0) + (ts - s);
    #pragma unroll
    for (int i = 0; i < 8; i++)
        if (base + i < n) S[base + i] = prefix + v[i];
    if (threadIdx.x == 0) part[blockIdx.x] = warpsum[7];
}

__global__ void scan2_k(int* part, int np) {
    __shared__ int sh[256];
    int t = threadIdx.x;
    int x = (t < np) ? part[t] : 0;
    sh[t] = x;
    __syncthreads();
    for (int o = 1; o < 256; o <<= 1) {
        int y = (t >= o) ? sh[t - o] : 0;
        __syncthreads();
        sh[t] += y;
        __syncthreads();
    }
    if (t < np) part[t] = sh[t] - x;  // exclusive
}

__global__ void scan3_k(int* __restrict__ S, const int* __restrict__ part, int n) {
    int t = blockIdx.x * blockDim.x + threadIdx.x;
    if (t < n) S[t] += part[t >> 11];
}

__global__ void weights_k(const int* __restrict__ din, const int* __restrict__ dout,
                          float* __restrict__ wdst, float* __restrict__ wsrc) {
    int t = blockIdx.x * blockDim.x + threadIdx.x;
    if (t < NTOT) {
        float d = (float)din[t];
        wdst[t] = (t < N_N) ? ((d > 0.f) ? rsqrtf(d) : 0.f)
                            : rsqrtf(fmaxf(d, 1.f));
    }
    if (t < DOUT_LEN) wsrc[t] = rsqrtf(fmaxf((float)dout[t], 1.f));
}

__global__ void fill_k(const int* __restrict__ src, const int* __restrict__ dst, int E,
                       const int* __restrict__ S, int row_base,
                       int* __restrict__ cnt, int* __restrict__ csr) {
    int e = blockIdx.x * blockDim.x + threadIdx.x;
    if (e >= E) return;
    int d = dst[e];
    int p = atomicAdd(&cnt[row_base + d], 1);
    csr[S[row_base + d] + p] = src[e];
}

// ---------------------------------------------------------------------------
// CSR pull SpMM: 2 rows per warp, 16 lanes/row, float4 payload, with
// shuffle-broadcast index staging: one coalesced 16-index load + one weight
// gather per 16 edges, then 16 independent LDG.128 row gathers (MLP ~16).
// out[r] = wdst[r] * sum_c wsrc[c]*in[c]
// ---------------------------------------------------------------------------
__global__ void pull_k(const int* __restrict__ S, const int* __restrict__ csr,
                       const float* __restrict__ wsrc, const float* __restrict__ wdst,
                       const float* __restrict__ in, float* __restrict__ out,
                       int nrows, int ostride, int ooff) {
    int r = (blockIdx.x * blockDim.x + threadIdx.x) >> 4;   // half-warp = row
    if (r >= nrows) return;
    int lane = threadIdx.x & 15;
    int base = threadIdx.x & 16;   // 0 or 16: this half-warp's lane base
    const unsigned FULL = 0xffffffffu;

    int s = S[r], e = S[r + 1];
    int deg = e - s;
    // both half-warps must iterate together (shfl participation)
    int maxdeg = max(deg, __shfl_xor_sync(FULL, deg, 16));

    float4 acc = make_float4(0.f, 0.f, 0.f, 0.f);
    for (int chunk = 0; chunk < maxdeg; chunk += 16) {
        int rem = deg - chunk;                    // may be <= 0
        int idx = (lane < rem) ? csr[s + chunk + lane] : 0;
        float wv = (lane < rem) ? wsrc[idx] : 0.f;
        #pragma unroll
        for (int k = 0; k < 16; k++) {
            int   c = __shfl_sync(FULL, idx, base + k);
            float w = __shfl_sync(FULL, wv,  base + k);
            if (k < rem) {
                float4 v = *(const float4*)(in + (size_t)c * D + lane * 4);
                acc.x = fmaf(w, v.x, acc.x);
                acc.y = fmaf(w, v.y, acc.y);
                acc.z = fmaf(w, v.z, acc.z);
                acc.w = fmaf(w, v.w, acc.w);
            }
        }
    }
    float wd = wdst[r];
    float4 o = make_float4(acc.x * wd, acc.y * wd, acc.z * wd, acc.w * wd);
    *(float4*)(out + (size_t)r * ostride + ooff + lane * 4) = o;
}

// ---------------------------------------------------------------------------
// HAN attention via bf16 tensor-core GEMM (16-row tiles per warp).
// ---------------------------------------------------------------------------
constexpr int WT_STRIDE = 72;

__global__ void han_attn_k(const float* __restrict__ z, int n,
                           const float* __restrict__ W1, const float* __restrict__ b1,
                           const float* __restrict__ w2, float* __restrict__ wsum) {
    __shared__ __align__(16) __nv_bfloat16 Wt[HID * WT_STRIDE];
    __shared__ float b1s[HID];
    __shared__ float w2s[HID];
    __shared__ float r0s[256], r1s[256];

    for (int i = threadIdx.x; i < D * HID; i += blockDim.x) {
        int k = i >> 7, h = i & 127;
        Wt[h * WT_STRIDE + k] = __float2bfloat16(W1[i]);
    }
    if (threadIdx.x < HID) {
        b1s[threadIdx.x] = b1[threadIdx.x];
        w2s[threadIdx.x] = w2[threadIdx.x];
    }
    __syncthreads();

    int warp = threadIdx.x >> 5;
    int lane = threadIdx.x & 31;
    int g = lane >> 2;
    int tig = lane & 3;
    int ntiles = (2 * n) >> 4;

    float acc0 = 0.f, acc1 = 0.f;

    for (int tile = blockIdx.x * 8 + warp; tile < ntiles; tile += gridDim.x * 8) {
        const float* zb = z + (size_t)tile * 16 * D;
        uint32_t A[4][4];
        #pragma unroll
        for (int kt = 0; kt < 4; kt++) {
            int k0 = kt * 16 + tig * 2;
            float2 v;
            v = *(const float2*)(zb + g * D + k0);            A[kt][0] = pack_bf16(v.x, v.y);
            v = *(const float2*)(zb + (g + 8) * D + k0);      A[kt][1] = pack_bf16(v.x, v.y);
            v = *(const float2*)(zb + g * D + k0 + 8);        A[kt][2] = pack_bf16(v.x, v.y);
            v = *(const float2*)(zb + (g + 8) * D + k0 + 8);  A[kt][3] = pack_bf16(v.x, v.y);
        }
        float s0 = 0.f, s1 = 0.f;
        #pragma unroll
        for (int nt = 0; nt < 16; nt++) {
            float c[4] = {0.f, 0.f, 0.f, 0.f};
            const __nv_bfloat16* wrow = Wt + (nt * 8 + g) * WT_STRIDE;
            #pragma unroll
            for (int kt = 0; kt < 4; kt++) {
                uint32_t b0 = *(const uint32_t*)(wrow + kt * 16 + tig * 2);
                uint32_t b1v = *(const uint32_t*)(wrow + kt * 16 + tig * 2 + 8);
                mma16816(c, A[kt], b0, b1v);
            }
            int col0 = nt * 8 + tig * 2;
            float bb0 = b1s[col0], bb1 = b1s[col0 + 1];
            float ww0 = w2s[col0], ww1 = w2s[col0 + 1];
            s0 = fmaf(tanh_fast(c[0] + bb0), ww0, s0);
            s0 = fmaf(tanh_fast(c[1] + bb1), ww1, s0);
            s1 = fmaf(tanh_fast(c[2] + bb0), ww0, s1);
            s1 = fmaf(tanh_fast(c[3] + bb1), ww1, s1);
        }
        s0 += __shfl_xor_sync(0xffffffffu, s0, 1);
        s0 += __shfl_xor_sync(0xffffffffu, s0, 2);
        s1 += __shfl_xor_sync(0xffffffffu, s1, 1);
        s1 += __shfl_xor_sync(0xffffffffu, s1, 2);
        if (tig == 0) {
            float v = s0 + s1;
            if (g & 1) acc1 += v; else acc0 += v;
        }
    }

    r0s[threadIdx.x] = acc0;
    r1s[threadIdx.x] = acc1;
    __syncthreads();
    for (int s = blockDim.x >> 1; s > 0; s >>= 1) {
        if (threadIdx.x < s) {
            r0s[threadIdx.x] += r0s[threadIdx.x + s];
            r1s[threadIdx.x] += r1s[threadIdx.x + s];
        }
        __syncthreads();
    }
    if (threadIdx.x == 0) {
        atomicAdd(&wsum[0], r0s[0]);
        atomicAdd(&wsum[1], r1s[0]);
    }
}

__global__ void beta_k(const float* __restrict__ wsum, float inv_n, float* __restrict__ beta) {
    float a = wsum[0] * inv_n;
    float b = wsum[1] * inv_n;
    float m = fmaxf(a, b);
    float e0 = expf(a - m), e1 = expf(b - m);
    float inv = 1.f / (e0 + e1);
    beta[0] = e0 * inv;
    beta[1] = e1 * inv;
}

__global__ void zero_wsum_k(float* w) {
    if (threadIdx.x < 4) w[threadIdx.x] = 0.f;
}

// h[n,:] = beta0*z[n,0,:] + beta1*z[n,1,:]   (iteration 1 only)
__global__ void combine_k(const float* __restrict__ z, const float* __restrict__ beta,
                          float* __restrict__ h, int n) {
    int t = blockIdx.x * blockDim.x + threadIdx.x;
    if (t >= n * 16) return;
    int node = t >> 4;
    int c = t & 15;
    float b0 = beta[0], b1 = beta[1];
    float4 z0 = ((const float4*)z)[node * 32 + c];
    float4 z1 = ((const float4*)z)[node * 32 + 16 + c];
    float4 r;
    r.x = fmaf(b0, z0.x, b1 * z1.x);
    r.y = fmaf(b0, z0.y, b1 * z1.y);
    r.z = fmaf(b0, z0.z, b1 * z1.z);
    r.w = fmaf(b0, z0.w, b1 * z1.w);
    ((float4*)h)[t] = r;
}

// epilogue: iter-2 combine fused into the batched gathers
__global__ void out_k(const float* __restrict__ zu, const float* __restrict__ zi,
                      const float* __restrict__ ui, const float* __restrict__ beta,
                      const int* __restrict__ uidx, const int* __restrict__ iidx,
                      const int* __restrict__ nidx, float* __restrict__ out) {
    int t = blockIdx.x * blockDim.x + threadIdx.x;
    if (t >= B_N * 16) return;
    int b = t >> 4;
    int c = t & 15;
    const float4* zu4 = (const float4*)zu;
    const float4* zi4 = (const float4*)zi;
    const float4* ui4 = (const float4*)ui;
    float4* o4 = (float4*)out;
    float bU0 = beta[0], bU1 = beta[1], bI0 = beta[2], bI1 = beta[3];

    {
        int u = uidx[b];
        float4 z0 = zu4[u * 32 + c];
        float4 z1 = zu4[u * 32 + 16 + c];
        float4 g = ui4[u * 16 + c];
        float4 r;
        r.x = 0.5f * (fmaf(bU0, z0.x, bU1 * z1.x) + g.x);
        r.y = 0.5f * (fmaf(bU0, z0.y, bU1 * z1.y) + g.y);
        r.z = 0.5f * (fmaf(bU0, z0.z, bU1 * z1.z) + g.z);
        r.w = 0.5f * (fmaf(bU0, z0.w, bU1 * z1.w) + g.w);
        o4[t] = r;
    }
    {
        int it = iidx[b];
        float4 z0 = zi4[it * 32 + c];
        float4 z1 = zi4[it * 32 + 16 + c];
        float4 g = ui4[(U_N + it) * 16 + c];
        float4 r;
        r.x = 0.5f * (fmaf(bI0, z0.x, bI1 * z1.x) + g.x);
        r.y = 0.5f * (fmaf(bI0, z0.y, bI1 * z1.y) + g.y);
        r.z = 0.5f * (fmaf(bI0, z0.z, bI1 * z1.z) + g.z);
        r.w = 0.5f * (fmaf(bI0, z0.w, bI1 * z1.w) + g.w);
        o4[B_N * 16 + t] = r;
    }
    {
        int itn = iidx[nidx[b]];
        float4 z0 = zi4[itn * 32 + c];
        float4 z1 = zi4[itn * 32 + 16 + c];
        float4 g = ui4[(U_N + itn) * 16 + c];
        float4 r;
        r.x = 0.5f * (fmaf(bI0, z0.x, bI1 * z1.x) + g.x);
        r.y = 0.5f * (fmaf(bI0, z0.y, bI1 * z1.y) + g.y);
        r.z = 0.5f * (fmaf(bI0, z0.z, bI1 * z1.z) + g.z);
        r.w = 0.5f * (fmaf(bI0, z0.w, bI1 * z1.w) + g.w);
        o4[2 * B_N * 16 + t] = r;
    }
}

// ---------------------------------------------------------------------------
// Host
// ---------------------------------------------------------------------------
static inline int nblk(long long n) { return (int)((n + 255) / 256); }

extern "C" void kernel_launch(void* const* d_in, const int* in_sizes, int n_in,
                              void* d_out, int out_size) {
    const float* user_feat = (const float*)d_in[0];
    const float* item_feat = (const float*)d_in[1];
    const float* sa_u_W1   = (const float*)d_in[2];
    const float* sa_u_b1   = (const float*)d_in[3];
    const float* sa_u_w2   = (const float*)d_in[4];
    const float* sa_i_W1   = (const float*)d_in[5];
    const float* sa_i_b1   = (const float*)d_in[6];
    const float* sa_i_w2   = (const float*)d_in[7];
    const int*   ui_e      = (const int*)d_in[8];
    const int*   ue1       = (const int*)d_in[9];
    const int*   ue2       = (const int*)d_in[10];
    const int*   ie1       = (const int*)d_in[11];
    const int*   ie2       = (const int*)d_in[12];
    const int*   uidx      = (const int*)d_in[13];
    const int*   iidx      = (const int*)d_in[14];
    const int*   nidx      = (const int*)d_in[15];

    const int Eui = in_sizes[8]  / 2;   // 2,000,000
    const int Eu  = in_sizes[9]  / 2;   //   500,000
    const int Ei  = in_sizes[11] / 2;   // 1,000,000

    float *ui_a, *ui_b, *hu, *hi, *zu, *zi, *wdst, *wsrc, *wsum, *beta;
    int *ibuf, *S, *csr;
    cudaGetSymbolAddress((void**)&ui_a, g_ui_a);
    cudaGetSymbolAddress((void**)&ui_b, g_ui_b);
    cudaGetSymbolAddress((void**)&hu,   g_hu);
    cudaGetSymbolAddress((void**)&hi,   g_hi);
    cudaGetSymbolAddress((void**)&zu,   g_zu);
    cudaGetSymbolAddress((void**)&zi,   g_zi);
    cudaGetSymbolAddress((void**)&wdst, g_wdst);
    cudaGetSymbolAddress((void**)&wsrc, g_wsrc);
    cudaGetSymbolAddress((void**)&wsum, g_wsum);
    cudaGetSymbolAddress((void**)&beta, g_beta);
    cudaGetSymbolAddress((void**)&ibuf, g_int);
    cudaGetSymbolAddress((void**)&S,    g_S);
    cudaGetSymbolAddress((void**)&csr,  g_csr);

    int* deg  = ibuf + OFF_DEG;
    int* cnt  = ibuf + OFF_CNT;
    int* dout = ibuf + OFF_DOUT;
    int* part = ibuf + OFF_PART;

    const int T = 256;

    // ---- zero int scratch ----
    zero_i4_k<<<nblk(INT_TOT / 4), T>>>((int4*)ibuf, INT_TOT / 4);

    // ---- init features ----
    init_k<<<nblk((long long)N_N * 16), T>>>((const float4*)user_feat,
                                             (const float4*)item_feat,
                                             (float4*)ui_a, (float4*)hu, (float4*)hi);

    // ---- degree counts ----
    cnt_k<<<nblk(Eui), T>>>(ui_e,       Eui, deg + RB_GCN);
    cnt_k<<<nblk(Eu),  T>>>(ue1 + Eu,   Eu,  deg + RB_U1);
    cnt_k<<<nblk(Eu),  T>>>(ue2 + Eu,   Eu,  deg + RB_U2);
    cnt_k<<<nblk(Ei),  T>>>(ie1 + Ei,   Ei,  deg + RB_I1);
    cnt_k<<<nblk(Ei),  T>>>(ie2 + Ei,   Ei,  deg + RB_I2);
    cnt_k<<<nblk(Eu),  T>>>(ue1,        Eu,  dout + 0);
    cnt_k<<<nblk(Eu),  T>>>(ue2,        Eu,  dout + U_N);
    cnt_k<<<nblk(Ei),  T>>>(ie1,        Ei,  dout + 2 * U_N);
    cnt_k<<<nblk(Ei),  T>>>(ie2,        Ei,  dout + 2 * U_N + I_N);

    // ---- global exclusive scan -> CSR row offsets ----
    const int nchunks = (NSCAN + 2047) / 2048;  // 220
    scan1_k<<<nchunks, T>>>(deg, NSCAN, S, part);
    scan2_k<<<1, 256>>>(part, nchunks);
    scan3_k<<<nblk(NSCAN), T>>>(S, part, NSCAN);

    // ---- normalization weights ----
    weights_k<<<nblk(NTOT), T>>>(deg, dout, wdst, wsrc);

    // ---- CSR fill ----
    fill_k<<<nblk(Eui), T>>>(ui_e + Eui, ui_e,     Eui, S, RB_GCN, cnt, csr);
    fill_k<<<nblk(Eu),  T>>>(ue1,        ue1 + Eu, Eu,  S, RB_U1,  cnt, csr);
    fill_k<<<nblk(Eu),  T>>>(ue2,        ue2 + Eu, Eu,  S, RB_U2,  cnt, csr);
    fill_k<<<nblk(Ei),  T>>>(ie1,        ie1 + Ei, Ei,  S, RB_I1,  cnt, csr);
    fill_k<<<nblk(Ei),  T>>>(ie2,        ie2 + Ei, Ei,  S, RB_I2,  cnt, csr);

    // attention grids: 16-row tiles, 8 warps/block
    const int ntu = (2 * U_N) / 16, blk_u = (ntu + 7) / 8;
    const int nti = (2 * I_N) / 16, blk_i = (nti + 7) / 8;

    // ---- 2 propagation iterations ----
    const float* ui_in = ui_a;
    float* ui_out = ui_b;
    for (int iter = 0; iter < 2; ++iter) {
        pull_k<<<nblk((long long)N_N * 16), T>>>(S + RB_GCN, csr, wdst + RB_GCN,
                                                 wdst + RB_GCN, ui_in, ui_out,
                                                 N_N, 64, 0);
        pull_k<<<nblk((long long)U_N * 16), T>>>(S + RB_U1, csr, wsrc + 0,
                                                 wdst + RB_U1, hu, zu, U_N, 128, 0);
        pull_k<<<nblk((long long)U_N * 16), T>>>(S + RB_U2, csr, wsrc + U_N,
                                                 wdst + RB_U2, hu, zu, U_N, 128, 64);
        pull_k<<<nblk((long long)I_N * 16), T>>>(S + RB_I1, csr, wsrc + 2 * U_N,
                                                 wdst + RB_I1, hi, zi, I_N, 128, 0);
        pull_k<<<nblk((long long)I_N * 16), T>>>(S + RB_I2, csr, wsrc + 2 * U_N + I_N,
                                                 wdst + RB_I2, hi, zi, I_N, 128, 64);

        zero_wsum_k<<<1, 32>>>(wsum);
        han_attn_k<<<blk_u, 256>>>(zu, U_N, sa_u_W1, sa_u_b1, sa_u_w2, wsum + 0);
        beta_k<<<1, 1>>>(wsum + 0, 1.0f / U_N, beta + 0);
        han_attn_k<<<blk_i, 256>>>(zi, I_N, sa_i_W1, sa_i_b1, sa_i_w2, wsum + 2);
        beta_k<<<1, 1>>>(wsum + 2, 1.0f / I_N, beta + 2);

        if (iter == 0) {
            combine_k<<<nblk((long long)U_N * 16), T>>>(zu, beta + 0, hu, U_N);
            combine_k<<<nblk((long long)I_N * 16), T>>>(zi, beta + 2, hi, I_N);
        }

        const float* tmp = ui_in;
        ui_in = ui_out;
        ui_out = (float*)tmp;
    }

    // ---- epilogue ----
    out_k<<<nblk((long long)B_N * 16), T>>>(zu, zi, ui_in, beta,
                                            uidx, iidx, nidx, (float*)d_out);
}

// round 8
// speedup vs baseline: 1.1487x; 1.1487x over previous
#include <cuda_runtime.h>
#include <cuda_bf16.h>
#include <cstdint>

// Problem constants (fixed by the dataset)
constexpr int U_N  = 50000;
constexpr int I_N  = 100000;
constexpr int N_N  = 150000;   // U + I
constexpr int D    = 64;
constexpr int B_N  = 8192;
constexpr int HID  = 128;

constexpr int NTOT  = N_N + 2 * U_N + 2 * I_N;   // 450000 CSR rows (5 graphs)
constexpr int NSCAN = NTOT + 1;
constexpr int E_TOT = 5000000;

// int scratch layout
constexpr int OFF_DEG  = 0;
constexpr int DEG_PAD  = 450008;
constexpr int OFF_CNT  = DEG_PAD;
constexpr int CNT_PAD  = 450008;
constexpr int OFF_DOUT = OFF_CNT + CNT_PAD;
constexpr int DOUT_LEN = 2 * U_N + 2 * I_N;      // 300000
constexpr int OFF_PART = OFF_DOUT + DOUT_LEN;
constexpr int INT_TOT  = OFF_PART + 256;

// CSR row bases within the concatenated degree/scan vector
constexpr int RB_GCN = 0;
constexpr int RB_U1  = N_N;
constexpr int RB_U2  = N_N + U_N;
constexpr int RB_I1  = N_N + 2 * U_N;
constexpr int RB_I2  = N_N + 2 * U_N + I_N;

// attention tiling (16-row tiles, 8 warps/block, one tile per warp)
constexpr int NTU   = (2 * U_N) / 16;            // 6250
constexpr int NTI   = (2 * I_N) / 16;            // 12500
constexpr int BLK_U = (NTU + 7) / 8;             // 782
constexpr int BLK_I = (NTI + 7) / 8;             // 1563
constexpr int GRID_ATTN = BLK_U + BLK_I;         // 2345
constexpr int GRID_GCN  = (N_N * 16) / 256;      // 9375
constexpr int GRID_FUSE = GRID_ATTN + GRID_GCN;  // 11720

// ---------------------------------------------------------------------------
// Scratch (device globals: allocation-free)
// ---------------------------------------------------------------------------
__device__ __align__(256) float g_ui_a[N_N * D];
__device__ __align__(256) float g_ui_b[N_N * D];
__device__ __align__(256) float g_hu[U_N * D];
__device__ __align__(256) float g_hi[I_N * D];
__device__ __align__(256) float g_zu[U_N * 2 * D];
__device__ __align__(256) float g_zi[I_N * 2 * D];
__device__ __align__(256) float g_wdst[NTOT];
__device__ __align__(256) float g_wsrc[DOUT_LEN];
__device__ __align__(256) float g_wsum[4];
__device__ __align__(256) float g_beta[4];
__device__ __align__(256) int   g_int[INT_TOT];
__device__ __align__(256) int   g_S[NSCAN + 8];
__device__ __align__(256) int   g_csr[E_TOT];

// ---------------------------------------------------------------------------
// Helpers
// ---------------------------------------------------------------------------
__device__ __forceinline__ float tanh_fast(float x) {
    float y;
    asm("tanh.approx.f32 %0, %1;" : "=f"(y) : "f"(x));
    return y;
}
__device__ __forceinline__ uint32_t pack_bf16(float lo, float hi) {
    uint32_t r;
    asm("cvt.rn.bf16x2.f32 %0, %1, %2;" : "=r"(r) : "f"(hi), "f"(lo));
    return r;
}
__device__ __forceinline__ void mma16816(float c[4], const uint32_t a[4],
                                         uint32_t b0, uint32_t b1) {
    asm volatile(
        "mma.sync.aligned.m16n8k16.row.col.f32.bf16.bf16.f32 "
        "{%0,%1,%2,%3}, {%4,%5,%6,%7}, {%8,%9}, {%0,%1,%2,%3};"
        : "+f"(c[0]), "+f"(c[1]), "+f"(c[2]), "+f"(c[3])
        : "r"(a[0]), "r"(a[1]), "r"(a[2]), "r"(a[3]), "r"(b0), "r"(b1));
}

// ---------------------------------------------------------------------------
// Kernels
// ---------------------------------------------------------------------------
__global__ void zero_i4_k(int4* p, int n4) {
    int t = blockIdx.x * blockDim.x + threadIdx.x;
    if (t < n4) p[t] = make_int4(0, 0, 0, 0);
}

__global__ void init_k(const float4* __restrict__ uf, const float4* __restrict__ itf,
                       float4* __restrict__ ui, float4* __restrict__ hu,
                       float4* __restrict__ hi) {
    int t = blockIdx.x * blockDim.x + threadIdx.x;
    if (t >= N_N * 16) return;
    if (t < U_N * 16) {
        float4 v = uf[t];
        ui[t] = v; hu[t] = v;
    } else {
        float4 v = itf[t - U_N * 16];
        ui[t] = v; hi[t - U_N * 16] = v;
    }
}

__global__ void cnt_k(const int* __restrict__ idx, int E, int* __restrict__ deg) {
    int t = blockIdx.x * blockDim.x + threadIdx.x;
    if (t < E) atomicAdd(&deg[idx[t]], 1);
}

// --- 3-phase exclusive scan over NSCAN ints (chunk = 2048) ---
__global__ void scan1_k(const int* __restrict__ deg, int n,
                        int* __restrict__ S, int* __restrict__ part) {
    __shared__ int warpsum[8];
    int base = blockIdx.x * 2048 + threadIdx.x * 8;
    int v[8];
    int s = 0;
    #pragma unroll
    for (int i = 0; i < 8; i++) {
        int x = (base + i < n) ? deg[base + i] : 0;
        v[i] = s; s += x;
    }
    int lane = threadIdx.x & 31, w = threadIdx.x >> 5;
    int ts = s;
    #pragma unroll
    for (int o = 1; o < 32; o <<= 1) {
        int y = __shfl_up_sync(0xffffffffu, ts, o);
        if (lane >= o) ts += y;
    }
    if (lane == 31) warpsum[w] = ts;
    __syncthreads();
    if (w == 0 && lane < 8) {
        int x = warpsum[lane];
        #pragma unroll
        for (int o = 1; o < 8; o <<= 1) {
            int y = __shfl_up_sync(0xffu, x, o);
            if (lane >= o) x += y;
        }
        warpsum[lane] = x;
    }
    __syncthreads();
    int prefix = (w > 0 ? warpsum[w - 1] : 0) + (ts - s);
    #pragma unroll
    for (int i = 0; i < 8; i++)
        if (base + i < n) S[base + i] = prefix + v[i];
    if (threadIdx.x == 0) part[blockIdx.x] = warpsum[7];
}

__global__ void scan2_k(int* part, int np) {
    __shared__ int sh[256];
    int t = threadIdx.x;
    int x = (t < np) ? part[t] : 0;
    sh[t] = x;
    __syncthreads();
    for (int o = 1; o < 256; o <<= 1) {
        int y = (t >= o) ? sh[t - o] : 0;
        __syncthreads();
        sh[t] += y;
        __syncthreads();
    }
    if (t < np) part[t] = sh[t] - x;  // exclusive
}

__global__ void scan3_k(int* __restrict__ S, const int* __restrict__ part, int n) {
    int t = blockIdx.x * blockDim.x + threadIdx.x;
    if (t < n) S[t] += part[t >> 11];
}

__global__ void weights_k(const int* __restrict__ din, const int* __restrict__ dout,
                          float* __restrict__ wdst, float* __restrict__ wsrc) {
    int t = blockIdx.x * blockDim.x + threadIdx.x;
    if (t < NTOT) {
        float d = (float)din[t];
        wdst[t] = (t < N_N) ? ((d > 0.f) ? rsqrtf(d) : 0.f)
                            : rsqrtf(fmaxf(d, 1.f));
    }
    if (t < DOUT_LEN) wsrc[t] = rsqrtf(fmaxf((float)dout[t], 1.f));
}

__global__ void fill_k(const int* __restrict__ src, const int* __restrict__ dst, int E,
                       const int* __restrict__ S, int row_base,
                       int* __restrict__ cnt, int* __restrict__ csr) {
    int e = blockIdx.x * blockDim.x + threadIdx.x;
    if (e >= E) return;
    int d = dst[e];
    int p = atomicAdd(&cnt[row_base + d], 1);
    csr[S[row_base + d] + p] = src[e];
}

// ---------------------------------------------------------------------------
// CSR pull SpMM body: half-warp per row, float4 payload (R6 champion version)
// ---------------------------------------------------------------------------
__device__ __forceinline__ void pull_row(const int* __restrict__ S,
                                         const int* __restrict__ csr,
                                         const float* __restrict__ wsrc,
                                         const float* __restrict__ wdst,
                                         const float* __restrict__ in,
                                         float* __restrict__ out,
                                         int r, int lane, int ostride, int ooff) {
    int s = S[r], e = S[r + 1];
    float4 acc = make_float4(0.f, 0.f, 0.f, 0.f);
    int j = s;
    for (; j + 4 <= e; j += 4) {
        int c0 = csr[j], c1 = csr[j + 1], c2 = csr[j + 2], c3 = csr[j + 3];
        float w0 = wsrc[c0], w1 = wsrc[c1], w2 = wsrc[c2], w3 = wsrc[c3];
        float4 v0 = *(const float4*)(in + (size_t)c0 * D + lane * 4);
        float4 v1 = *(const float4*)(in + (size_t)c1 * D + lane * 4);
        float4 v2 = *(const float4*)(in + (size_t)c2 * D + lane * 4);
        float4 v3 = *(const float4*)(in + (size_t)c3 * D + lane * 4);
        acc.x = fmaf(w0, v0.x, acc.x); acc.y = fmaf(w0, v0.y, acc.y);
        acc.z = fmaf(w0, v0.z, acc.z); acc.w = fmaf(w0, v0.w, acc.w);
        acc.x = fmaf(w1, v1.x, acc.x); acc.y = fmaf(w1, v1.y, acc.y);
        acc.z = fmaf(w1, v1.z, acc.z); acc.w = fmaf(w1, v1.w, acc.w);
        acc.x = fmaf(w2, v2.x, acc.x); acc.y = fmaf(w2, v2.y, acc.y);
        acc.z = fmaf(w2, v2.z, acc.z); acc.w = fmaf(w2, v2.w, acc.w);
        acc.x = fmaf(w3, v3.x, acc.x); acc.y = fmaf(w3, v3.y, acc.y);
        acc.z = fmaf(w3, v3.z, acc.z); acc.w = fmaf(w3, v3.w, acc.w);
    }
    for (; j < e; j++) {
        int c = csr[j];
        float w = wsrc[c];
        float4 v = *(const float4*)(in + (size_t)c * D + lane * 4);
        acc.x = fmaf(w, v.x, acc.x); acc.y = fmaf(w, v.y, acc.y);
        acc.z = fmaf(w, v.z, acc.z); acc.w = fmaf(w, v.w, acc.w);
    }
    float wd = wdst[r];
    float4 o = make_float4(acc.x * wd, acc.y * wd, acc.z * wd, acc.w * wd);
    *(float4*)(out + (size_t)r * ostride + ooff + lane * 4) = o;
}

__global__ void pull_k(const int* __restrict__ S, const int* __restrict__ csr,
                       const float* __restrict__ wsrc, const float* __restrict__ wdst,
                       const float* __restrict__ in, float* __restrict__ out,
                       int nrows, int ostride, int ooff) {
    int r = (blockIdx.x * blockDim.x + threadIdx.x) >> 4;
    if (r >= nrows) return;
    pull_row(S, csr, wsrc, wdst, in, out, r, threadIdx.x & 15, ostride, ooff);
}

// ---------------------------------------------------------------------------
// FUSED: HAN attention (user+item, tensor cores) co-resident with gcn pull.
// Blocks [0, GRID_ATTN) do attention tiles; blocks [GRID_ATTN, GRID_FUSE)
// do the gcn-graph CSR pull. The two are data-independent; co-running hides
// the attention (tensor/MUFU/FMA) under the gcn gathers (LSU/L2).
// ---------------------------------------------------------------------------
constexpr int WT_STRIDE = 72;

__global__ void gcn_attn_k(const float* __restrict__ ui_in, float* __restrict__ ui_out,
                           const float* __restrict__ W1u, const float* __restrict__ b1u,
                           const float* __restrict__ w2u,
                           const float* __restrict__ W1i, const float* __restrict__ b1i,
                           const float* __restrict__ w2i) {
    if (blockIdx.x >= GRID_ATTN) {
        // ---- gcn pull path ----
        int gid = (blockIdx.x - GRID_ATTN) * blockDim.x + threadIdx.x;
        int r = gid >> 4;
        if (r < N_N)
            pull_row(g_S + RB_GCN, g_csr, g_wdst + RB_GCN, g_wdst + RB_GCN,
                     ui_in, ui_out, r, gid & 15, 64, 0);
        return;
    }

    // ---- attention path ----
    bool isU = blockIdx.x < BLK_U;
    const float* z  = isU ? g_zu : g_zi;
    const float* W1 = isU ? W1u : W1i;
    const float* b1 = isU ? b1u : b1i;
    const float* w2 = isU ? w2u : w2i;
    int ntiles = isU ? NTU : NTI;
    int bid    = isU ? blockIdx.x : blockIdx.x - BLK_U;
    float* wsp = g_wsum + (isU ? 0 : 2);

    __shared__ __align__(16) __nv_bfloat16 Wt[HID * WT_STRIDE];
    __shared__ float b1s[HID];
    __shared__ float w2s[HID];
    __shared__ float r0s[256], r1s[256];

    for (int i = threadIdx.x; i < D * HID; i += blockDim.x) {
        int k = i >> 7, h = i & 127;
        Wt[h * WT_STRIDE + k] = __float2bfloat16(W1[i]);
    }
    if (threadIdx.x < HID) {
        b1s[threadIdx.x] = b1[threadIdx.x];
        w2s[threadIdx.x] = w2[threadIdx.x];
    }
    __syncthreads();

    int warp = threadIdx.x >> 5;
    int lane = threadIdx.x & 31;
    int g = lane >> 2;
    int tig = lane & 3;
    int tile = bid * 8 + warp;

    float acc0 = 0.f, acc1 = 0.f;

    if (tile < ntiles) {
        const float* zb = z + (size_t)tile * 16 * D;
        uint32_t A[4][4];
        #pragma unroll
        for (int kt = 0; kt < 4; kt++) {
            int k0 = kt * 16 + tig * 2;
            float2 v;
            v = *(const float2*)(zb + g * D + k0);            A[kt][0] = pack_bf16(v.x, v.y);
            v = *(const float2*)(zb + (g + 8) * D + k0);      A[kt][1] = pack_bf16(v.x, v.y);
            v = *(const float2*)(zb + g * D + k0 + 8);        A[kt][2] = pack_bf16(v.x, v.y);
            v = *(const float2*)(zb + (g + 8) * D + k0 + 8);  A[kt][3] = pack_bf16(v.x, v.y);
        }
        float s0 = 0.f, s1 = 0.f;
        #pragma unroll
        for (int nt = 0; nt < 16; nt++) {
            float c[4] = {0.f, 0.f, 0.f, 0.f};
            const __nv_bfloat16* wrow = Wt + (nt * 8 + g) * WT_STRIDE;
            #pragma unroll
            for (int kt = 0; kt < 4; kt++) {
                uint32_t b0 = *(const uint32_t*)(wrow + kt * 16 + tig * 2);
                uint32_t b1v = *(const uint32_t*)(wrow + kt * 16 + tig * 2 + 8);
                mma16816(c, A[kt], b0, b1v);
            }
            int col0 = nt * 8 + tig * 2;
            float bb0 = b1s[col0], bb1 = b1s[col0 + 1];
            float ww0 = w2s[col0], ww1 = w2s[col0 + 1];
            s0 = fmaf(tanh_fast(c[0] + bb0), ww0, s0);
            s0 = fmaf(tanh_fast(c[1] + bb1), ww1, s0);
            s1 = fmaf(tanh_fast(c[2] + bb0), ww0, s1);
            s1 = fmaf(tanh_fast(c[3] + bb1), ww1, s1);
        }
        s0 += __shfl_xor_sync(0xffffffffu, s0, 1);
        s0 += __shfl_xor_sync(0xffffffffu, s0, 2);
        s1 += __shfl_xor_sync(0xffffffffu, s1, 1);
        s1 += __shfl_xor_sync(0xffffffffu, s1, 2);
        if (tig == 0) {
            float v = s0 + s1;
            if (g & 1) acc1 += v; else acc0 += v;
        }
    }

    r0s[threadIdx.x] = acc0;
    r1s[threadIdx.x] = acc1;
    __syncthreads();
    for (int s = blockDim.x >> 1; s > 0; s >>= 1) {
        if (threadIdx.x < s) {
            r0s[threadIdx.x] += r0s[threadIdx.x + s];
            r1s[threadIdx.x] += r1s[threadIdx.x + s];
        }
        __syncthreads();
    }
    if (threadIdx.x == 0) {
        atomicAdd(&wsp[0], r0s[0]);
        atomicAdd(&wsp[1], r1s[0]);
    }
}

// both betas in one tiny launch
__global__ void beta2_k(const float* __restrict__ wsum, float* __restrict__ beta) {
    int t = threadIdx.x;
    if (t < 2) {
        float inv_n = (t == 0) ? (1.0f / U_N) : (1.0f / I_N);
        float a = wsum[2 * t] * inv_n;
        float b = wsum[2 * t + 1] * inv_n;
        float m = fmaxf(a, b);
        float e0 = expf(a - m), e1 = expf(b - m);
        float inv = 1.f / (e0 + e1);
        beta[2 * t]     = e0 * inv;
        beta[2 * t + 1] = e1 * inv;
    }
}

__global__ void zero_wsum_k(float* w) {
    if (threadIdx.x < 4) w[threadIdx.x] = 0.f;
}

// h[n,:] = beta0*z[n,0,:] + beta1*z[n,1,:]   (iteration 1 only)
__global__ void combine_k(const float* __restrict__ z, const float* __restrict__ beta,
                          float* __restrict__ h, int n) {
    int t = blockIdx.x * blockDim.x + threadIdx.x;
    if (t >= n * 16) return;
    int node = t >> 4;
    int c = t & 15;
    float b0 = beta[0], b1 = beta[1];
    float4 z0 = ((const float4*)z)[node * 32 + c];
    float4 z1 = ((const float4*)z)[node * 32 + 16 + c];
    float4 r;
    r.x = fmaf(b0, z0.x, b1 * z1.x);
    r.y = fmaf(b0, z0.y, b1 * z1.y);
    r.z = fmaf(b0, z0.z, b1 * z1.z);
    r.w = fmaf(b0, z0.w, b1 * z1.w);
    ((float4*)h)[t] = r;
}

// epilogue: iter-2 combine fused into the batched gathers
__global__ void out_k(const float* __restrict__ zu, const float* __restrict__ zi,
                      const float* __restrict__ ui, const float* __restrict__ beta,
                      const int* __restrict__ uidx, const int* __restrict__ iidx,
                      const int* __restrict__ nidx, float* __restrict__ out) {
    int t = blockIdx.x * blockDim.x + threadIdx.x;
    if (t >= B_N * 16) return;
    int b = t >> 4;
    int c = t & 15;
    const float4* zu4 = (const float4*)zu;
    const float4* zi4 = (const float4*)zi;
    const float4* ui4 = (const float4*)ui;
    float4* o4 = (float4*)out;
    float bU0 = beta[0], bU1 = beta[1], bI0 = beta[2], bI1 = beta[3];

    {
        int u = uidx[b];
        float4 z0 = zu4[u * 32 + c];
        float4 z1 = zu4[u * 32 + 16 + c];
        float4 g = ui4[u * 16 + c];
        float4 r;
        r.x = 0.5f * (fmaf(bU0, z0.x, bU1 * z1.x) + g.x);
        r.y = 0.5f * (fmaf(bU0, z0.y, bU1 * z1.y) + g.y);
        r.z = 0.5f * (fmaf(bU0, z0.z, bU1 * z1.z) + g.z);
        r.w = 0.5f * (fmaf(bU0, z0.w, bU1 * z1.w) + g.w);
        o4[t] = r;
    }
    {
        int it = iidx[b];
        float4 z0 = zi4[it * 32 + c];
        float4 z1 = zi4[it * 32 + 16 + c];
        float4 g = ui4[(U_N + it) * 16 + c];
        float4 r;
        r.x = 0.5f * (fmaf(bI0, z0.x, bI1 * z1.x) + g.x);
        r.y = 0.5f * (fmaf(bI0, z0.y, bI1 * z1.y) + g.y);
        r.z = 0.5f * (fmaf(bI0, z0.z, bI1 * z1.z) + g.z);
        r.w = 0.5f * (fmaf(bI0, z0.w, bI1 * z1.w) + g.w);
        o4[B_N * 16 + t] = r;
    }
    {
        int itn = iidx[nidx[b]];
        float4 z0 = zi4[itn * 32 + c];
        float4 z1 = zi4[itn * 32 + 16 + c];
        float4 g = ui4[(U_N + itn) * 16 + c];
        float4 r;
        r.x = 0.5f * (fmaf(bI0, z0.x, bI1 * z1.x) + g.x);
        r.y = 0.5f * (fmaf(bI0, z0.y, bI1 * z1.y) + g.y);
        r.z = 0.5f * (fmaf(bI0, z0.z, bI1 * z1.z) + g.z);
        r.w = 0.5f * (fmaf(bI0, z0.w, bI1 * z1.w) + g.w);
        o4[2 * B_N * 16 + t] = r;
    }
}

// ---------------------------------------------------------------------------
// Host
// ---------------------------------------------------------------------------
static inline int nblk(long long n) { return (int)((n + 255) / 256); }

extern "C" void kernel_launch(void* const* d_in, const int* in_sizes, int n_in,
                              void* d_out, int out_size) {
    const float* user_feat = (const float*)d_in[0];
    const float* item_feat = (const float*)d_in[1];
    const float* sa_u_W1   = (const float*)d_in[2];
    const float* sa_u_b1   = (const float*)d_in[3];
    const float* sa_u_w2   = (const float*)d_in[4];
    const float* sa_i_W1   = (const float*)d_in[5];
    const float* sa_i_b1   = (const float*)d_in[6];
    const float* sa_i_w2   = (const float*)d_in[7];
    const int*   ui_e      = (const int*)d_in[8];
    const int*   ue1       = (const int*)d_in[9];
    const int*   ue2       = (const int*)d_in[10];
    const int*   ie1       = (const int*)d_in[11];
    const int*   ie2       = (const int*)d_in[12];
    const int*   uidx      = (const int*)d_in[13];
    const int*   iidx      = (const int*)d_in[14];
    const int*   nidx      = (const int*)d_in[15];

    const int Eui = in_sizes[8]  / 2;   // 2,000,000
    const int Eu  = in_sizes[9]  / 2;   //   500,000
    const int Ei  = in_sizes[11] / 2;   // 1,000,000

    float *ui_a, *ui_b, *hu, *hi, *zu, *zi, *wdst, *wsrc, *wsum, *beta;
    int *ibuf, *S, *csr;
    cudaGetSymbolAddress((void**)&ui_a, g_ui_a);
    cudaGetSymbolAddress((void**)&ui_b, g_ui_b);
    cudaGetSymbolAddress((void**)&hu,   g_hu);
    cudaGetSymbolAddress((void**)&hi,   g_hi);
    cudaGetSymbolAddress((void**)&zu,   g_zu);
    cudaGetSymbolAddress((void**)&zi,   g_zi);
    cudaGetSymbolAddress((void**)&wdst, g_wdst);
    cudaGetSymbolAddress((void**)&wsrc, g_wsrc);
    cudaGetSymbolAddress((void**)&wsum, g_wsum);
    cudaGetSymbolAddress((void**)&beta, g_beta);
    cudaGetSymbolAddress((void**)&ibuf, g_int);
    cudaGetSymbolAddress((void**)&S,    g_S);
    cudaGetSymbolAddress((void**)&csr,  g_csr);

    int* deg  = ibuf + OFF_DEG;
    int* cnt  = ibuf + OFF_CNT;
    int* dout = ibuf + OFF_DOUT;
    int* part = ibuf + OFF_PART;

    const int T = 256;

    // ---- zero int scratch ----
    zero_i4_k<<<nblk(INT_TOT / 4), T>>>((int4*)ibuf, INT_TOT / 4);

    // ---- init features ----
    init_k<<<nblk((long long)N_N * 16), T>>>((const float4*)user_feat,
                                             (const float4*)item_feat,
                                             (float4*)ui_a, (float4*)hu, (float4*)hi);

    // ---- degree counts ----
    cnt_k<<<nblk(Eui), T>>>(ui_e,       Eui, deg + RB_GCN);
    cnt_k<<<nblk(Eu),  T>>>(ue1 + Eu,   Eu,  deg + RB_U1);
    cnt_k<<<nblk(Eu),  T>>>(ue2 + Eu,   Eu,  deg + RB_U2);
    cnt_k<<<nblk(Ei),  T>>>(ie1 + Ei,   Ei,  deg + RB_I1);
    cnt_k<<<nblk(Ei),  T>>>(ie2 + Ei,   Ei,  deg + RB_I2);
    cnt_k<<<nblk(Eu),  T>>>(ue1,        Eu,  dout + 0);
    cnt_k<<<nblk(Eu),  T>>>(ue2,        Eu,  dout + U_N);
    cnt_k<<<nblk(Ei),  T>>>(ie1,        Ei,  dout + 2 * U_N);
    cnt_k<<<nblk(Ei),  T>>>(ie2,        Ei,  dout + 2 * U_N + I_N);

    // ---- global exclusive scan -> CSR row offsets ----
    const int nchunks = (NSCAN + 2047) / 2048;  // 220
    scan1_k<<<nchunks, T>>>(deg, NSCAN, S, part);
    scan2_k<<<1, 256>>>(part, nchunks);
    scan3_k<<<nblk(NSCAN), T>>>(S, part, NSCAN);

    // ---- normalization weights ----
    weights_k<<<nblk(NTOT), T>>>(deg, dout, wdst, wsrc);

    // ---- CSR fill ----
    fill_k<<<nblk(Eui), T>>>(ui_e + Eui, ui_e,     Eui, S, RB_GCN, cnt, csr);
    fill_k<<<nblk(Eu),  T>>>(ue1,        ue1 + Eu, Eu,  S, RB_U1,  cnt, csr);
    fill_k<<<nblk(Eu),  T>>>(ue2,        ue2 + Eu, Eu,  S, RB_U2,  cnt, csr);
    fill_k<<<nblk(Ei),  T>>>(ie1,        ie1 + Ei, Ei,  S, RB_I1,  cnt, csr);
    fill_k<<<nblk(Ei),  T>>>(ie2,        ie2 + Ei, Ei,  S, RB_I2,  cnt, csr);

    // ---- 2 propagation iterations ----
    const float* ui_in = ui_a;
    float* ui_out = ui_b;
    for (int iter = 0; iter < 2; ++iter) {
        // HAN metapath pulls (produce zu, zi)
        pull_k<<<nblk((long long)U_N * 16), T>>>(S + RB_U1, csr, wsrc + 0,
                                                 wdst + RB_U1, hu, zu, U_N, 128, 0);
        pull_k<<<nblk((long long)U_N * 16), T>>>(S + RB_U2, csr, wsrc + U_N,
                                                 wdst + RB_U2, hu, zu, U_N, 128, 64);
        pull_k<<<nblk((long long)I_N * 16), T>>>(S + RB_I1, csr, wsrc + 2 * U_N,
                                                 wdst + RB_I1, hi, zi, I_N, 128, 0);
        pull_k<<<nblk((long long)I_N * 16), T>>>(S + RB_I2, csr, wsrc + 2 * U_N + I_N,
                                                 wdst + RB_I2, hi, zi, I_N, 128, 64);

        zero_wsum_k<<<1, 32>>>(wsum);
        // fused: attention (zu/zi) co-resident with gcn pull (ui_in -> ui_out)
        gcn_attn_k<<<GRID_FUSE, 256>>>(ui_in, ui_out,
                                       sa_u_W1, sa_u_b1, sa_u_w2,
                                       sa_i_W1, sa_i_b1, sa_i_w2);
        beta2_k<<<1, 32>>>(wsum, beta);

        if (iter == 0) {
            combine_k<<<nblk((long long)U_N * 16), T>>>(zu, beta + 0, hu, U_N);
            combine_k<<<nblk((long long)I_N * 16), T>>>(zi, beta + 2, hi, I_N);
        }

        const float* tmp = ui_in;
        ui_in = ui_out;
        ui_out = (float*)tmp;
    }

    // ---- epilogue ----
    out_k<<<nblk((long long)B_N * 16), T>>>(zu, zi, ui_in, beta,
                                            uidx, iidx, nidx, (float*)d_out);
}

// round 9
// speedup vs baseline: 1.2414x; 1.0807x over previous
#include <cuda_runtime.h>
#include <cuda_bf16.h>
#include <cstdint>

// Problem constants (fixed by the dataset)
constexpr int U_N  = 50000;
constexpr int I_N  = 100000;
constexpr int N_N  = 150000;   // U + I
constexpr int D    = 64;
constexpr int B_N  = 8192;
constexpr int HID  = 128;

constexpr int NTOT  = N_N + 2 * U_N + 2 * I_N;   // 450000 CSR rows (5 graphs)
constexpr int NSCAN = NTOT + 1;
constexpr int E_TOT = 5000000;

// int scratch layout
constexpr int OFF_DEG  = 0;
constexpr int DEG_PAD  = 450008;
constexpr int OFF_CNT  = DEG_PAD;                // cursor array (init = S by scan3w)
constexpr int CNT_PAD  = 450008;
constexpr int OFF_DOUT = OFF_CNT + CNT_PAD;
constexpr int DOUT_LEN = 2 * U_N + 2 * I_N;      // 300000
constexpr int OFF_PART = OFF_DOUT + DOUT_LEN;
constexpr int INT_TOT  = OFF_PART + 256;

// CSR row bases within the concatenated degree/scan vector
constexpr int RB_GCN = 0;
constexpr int RB_U1  = N_N;
constexpr int RB_U2  = N_N + U_N;
constexpr int RB_I1  = N_N + 2 * U_N;
constexpr int RB_I2  = N_N + 2 * U_N + I_N;

// attention tiling (16-row tiles, 8 warps/block, one tile per warp)
constexpr int NTU   = (2 * U_N) / 16;            // 6250
constexpr int NTI   = (2 * I_N) / 16;            // 12500
constexpr int BLK_U = (NTU + 7) / 8;             // 782
constexpr int BLK_I = (NTI + 7) / 8;             // 1563
constexpr int GRID_ATTN = BLK_U + BLK_I;         // 2345
constexpr int GRID_GCN  = (N_N * 16) / 256;      // 9375
constexpr int GRID_FUSE = GRID_ATTN + GRID_GCN;  // 11720

// ---------------------------------------------------------------------------
// Scratch (device globals: allocation-free)
// ---------------------------------------------------------------------------
__device__ __align__(256) float g_ui_a[N_N * D];
__device__ __align__(256) float g_ui_b[N_N * D];
__device__ __align__(256) float g_hu[U_N * D];
__device__ __align__(256) float g_hi[I_N * D];
__device__ __align__(256) float g_zu[U_N * 2 * D];
__device__ __align__(256) float g_zi[I_N * 2 * D];
__device__ __align__(256) float g_wdst[NTOT];
__device__ __align__(256) float g_wsrc[DOUT_LEN];
__device__ __align__(256) float g_wsum[4];
__device__ __align__(256) float g_beta[4];
__device__ __align__(256) int   g_int[INT_TOT];
__device__ __align__(256) int   g_S[NSCAN + 8];
__device__ __align__(256) int   g_csr[E_TOT];

// ---------------------------------------------------------------------------
// Helpers
// ---------------------------------------------------------------------------
__device__ __forceinline__ float tanh_fast(float x) {
    float y;
    asm("tanh.approx.f32 %0, %1;" : "=f"(y) : "f"(x));
    return y;
}
__device__ __forceinline__ uint32_t pack_bf16(float lo, float hi) {
    uint32_t r;
    asm("cvt.rn.bf16x2.f32 %0, %1, %2;" : "=r"(r) : "f"(hi), "f"(lo));
    return r;
}
__device__ __forceinline__ void mma16816(float c[4], const uint32_t a[4],
                                         uint32_t b0, uint32_t b1) {
    asm volatile(
        "mma.sync.aligned.m16n8k16.row.col.f32.bf16.bf16.f32 "
        "{%0,%1,%2,%3}, {%4,%5,%6,%7}, {%8,%9}, {%0,%1,%2,%3};"
        : "+f"(c[0]), "+f"(c[1]), "+f"(c[2]), "+f"(c[3])
        : "r"(a[0]), "r"(a[1]), "r"(a[2]), "r"(a[3]), "r"(b0), "r"(b1));
}

// ---------------------------------------------------------------------------
// Kernels
// ---------------------------------------------------------------------------
__global__ void zero_i4_k(int4* p, int n4) {
    int t = blockIdx.x * blockDim.x + threadIdx.x;
    if (t < n4) p[t] = make_int4(0, 0, 0, 0);
}

__global__ void init_k(const float4* __restrict__ uf, const float4* __restrict__ itf,
                       float4* __restrict__ ui, float4* __restrict__ hu,
                       float4* __restrict__ hi) {
    int t = blockIdx.x * blockDim.x + threadIdx.x;
    if (t >= N_N * 16) return;
    if (t < U_N * 16) {
        float4 v = uf[t];
        ui[t] = v; hu[t] = v;
    } else {
        float4 v = itf[t - U_N * 16];
        ui[t] = v; hi[t - U_N * 16] = v;
    }
}

// ---------------------------------------------------------------------------
// Fused degree counting: 9 jobs, 4 edges per thread (atomic MLP = 4)
// ---------------------------------------------------------------------------
struct CntJobs {
    const int* ptr[9];
    int        dego[9];   // offset into g_int
    int        E[9];      // edge counts
    int        qcum[10];  // cumulative quad-thread offsets
};

__global__ void cnt_all_k(CntJobs J) {
    int t = blockIdx.x * blockDim.x + threadIdx.x;
    if (t >= J.qcum[9]) return;
    int j = 0;
    #pragma unroll
    for (int k = 1; k < 9; k++) j += (t >= J.qcum[k]);
    int e0 = (t - J.qcum[j]) * 4;
    int E = J.E[j];
    const int* p = J.ptr[j];
    int* base = g_int + J.dego[j];
    #pragma unroll
    for (int i = 0; i < 4; i++) {
        int e = e0 + i;
        if (e < E) atomicAdd(&base[p[e]], 1);
    }
}

// --- 3-phase exclusive scan over NSCAN ints (chunk = 2048) ---
__global__ void scan1_k(const int* __restrict__ deg, int n,
                        int* __restrict__ S, int* __restrict__ part) {
    __shared__ int warpsum[8];
    int base = blockIdx.x * 2048 + threadIdx.x * 8;
    int v[8];
    int s = 0;
    #pragma unroll
    for (int i = 0; i < 8; i++) {
        int x = (base + i < n) ? deg[base + i] : 0;
        v[i] = s; s += x;
    }
    int lane = threadIdx.x & 31, w = threadIdx.x >> 5;
    int ts = s;
    #pragma unroll
    for (int o = 1; o < 32; o <<= 1) {
        int y = __shfl_up_sync(0xffffffffu, ts, o);
        if (lane >= o) ts += y;
    }
    if (lane == 31) warpsum[w] = ts;
    __syncthreads();
    if (w == 0 && lane < 8) {
        int x = warpsum[lane];
        #pragma unroll
        for (int o = 1; o < 8; o <<= 1) {
            int y = __shfl_up_sync(0xffu, x, o);
            if (lane >= o) x += y;
        }
        warpsum[lane] = x;
    }
    __syncthreads();
    int prefix = (w > 0 ? warpsum[w - 1] : 0) + (ts - s);
    #pragma unroll
    for (int i = 0; i < 8; i++)
        if (base + i < n) S[base + i] = prefix + v[i];
    if (threadIdx.x == 0) part[blockIdx.x] = warpsum[7];
}

__global__ void scan2_k(int* part, int np) {
    __shared__ int sh[256];
    int t = threadIdx.x;
    int x = (t < np) ? part[t] : 0;
    sh[t] = x;
    __syncthreads();
    for (int o = 1; o < 256; o <<= 1) {
        int y = (t >= o) ? sh[t - o] : 0;
        __syncthreads();
        sh[t] += y;
        __syncthreads();
    }
    if (t < np) part[t] = sh[t] - x;  // exclusive
}

// scan finalize + cursor init (cur = S) + normalization weights (fused)
__global__ void scan3w_k() {
    int t = blockIdx.x * blockDim.x + threadIdx.x;
    if (t < NSCAN) {
        int sv = g_S[t] + g_int[OFF_PART + (t >> 11)];
        g_S[t] = sv;
        if (t < NTOT) g_int[OFF_CNT + t] = sv;   // fill cursor starts at row base
    }
    if (t < NTOT) {
        float d = (float)g_int[OFF_DEG + t];
        g_wdst[t] = (t < N_N) ? ((d > 0.f) ? rsqrtf(d) : 0.f)
                              : rsqrtf(fmaxf(d, 1.f));
    }
    if (t < DOUT_LEN) g_wsrc[t] = rsqrtf(fmaxf((float)g_int[OFF_DOUT + t], 1.f));
}

// ---------------------------------------------------------------------------
// Fused CSR fill: 5 jobs, 4 edges per thread, direct global cursor (no S load)
// ---------------------------------------------------------------------------
struct FillJobs {
    const int* src[5];
    const int* dst[5];
    int        rb[5];
    int        E[5];
    int        qcum[6];
};

__global__ void fill_all_k(FillJobs J) {
    int t = blockIdx.x * blockDim.x + threadIdx.x;
    if (t >= J.qcum[5]) return;
    int j = 0;
    #pragma unroll
    for (int k = 1; k < 5; k++) j += (t >= J.qcum[k]);
    int e0 = (t - J.qcum[j]) * 4;
    int E = J.E[j];
    const int* src = J.src[j];
    const int* dst = J.dst[j];
    int* cur = g_int + OFF_CNT + J.rb[j];
    #pragma unroll
    for (int i = 0; i < 4; i++) {
        int e = e0 + i;
        if (e < E) {
            int p = atomicAdd(&cur[dst[e]], 1);
            g_csr[p] = src[e];
        }
    }
}

// ---------------------------------------------------------------------------
// CSR pull SpMM body: half-warp per row, float4 payload (R6 champion version)
// ---------------------------------------------------------------------------
__device__ __forceinline__ void pull_row(const int* __restrict__ S,
                                         const int* __restrict__ csr,
                                         const float* __restrict__ wsrc,
                                         const float* __restrict__ wdst,
                                         const float* __restrict__ in,
                                         float* __restrict__ out,
                                         int r, int lane, int ostride, int ooff) {
    int s = S[r], e = S[r + 1];
    float4 acc = make_float4(0.f, 0.f, 0.f, 0.f);
    int j = s;
    for (; j + 4 <= e; j += 4) {
        int c0 = csr[j], c1 = csr[j + 1], c2 = csr[j + 2], c3 = csr[j + 3];
        float w0 = wsrc[c0], w1 = wsrc[c1], w2 = wsrc[c2], w3 = wsrc[c3];
        float4 v0 = *(const float4*)(in + (size_t)c0 * D + lane * 4);
        float4 v1 = *(const float4*)(in + (size_t)c1 * D + lane * 4);
        float4 v2 = *(const float4*)(in + (size_t)c2 * D + lane * 4);
        float4 v3 = *(const float4*)(in + (size_t)c3 * D + lane * 4);
        acc.x = fmaf(w0, v0.x, acc.x); acc.y = fmaf(w0, v0.y, acc.y);
        acc.z = fmaf(w0, v0.z, acc.z); acc.w = fmaf(w0, v0.w, acc.w);
        acc.x = fmaf(w1, v1.x, acc.x); acc.y = fmaf(w1, v1.y, acc.y);
        acc.z = fmaf(w1, v1.z, acc.z); acc.w = fmaf(w1, v1.w, acc.w);
        acc.x = fmaf(w2, v2.x, acc.x); acc.y = fmaf(w2, v2.y, acc.y);
        acc.z = fmaf(w2, v2.z, acc.z); acc.w = fmaf(w2, v2.w, acc.w);
        acc.x = fmaf(w3, v3.x, acc.x); acc.y = fmaf(w3, v3.y, acc.y);
        acc.z = fmaf(w3, v3.z, acc.z); acc.w = fmaf(w3, v3.w, acc.w);
    }
    for (; j < e; j++) {
        int c = csr[j];
        float w = wsrc[c];
        float4 v = *(const float4*)(in + (size_t)c * D + lane * 4);
        acc.x = fmaf(w, v.x, acc.x); acc.y = fmaf(w, v.y, acc.y);
        acc.z = fmaf(w, v.z, acc.z); acc.w = fmaf(w, v.w, acc.w);
    }
    float wd = wdst[r];
    float4 o = make_float4(acc.x * wd, acc.y * wd, acc.z * wd, acc.w * wd);
    *(float4*)(out + (size_t)r * ostride + ooff + lane * 4) = o;
}

__global__ void pull_k(const int* __restrict__ S, const int* __restrict__ csr,
                       const float* __restrict__ wsrc, const float* __restrict__ wdst,
                       const float* __restrict__ in, float* __restrict__ out,
                       int nrows, int ostride, int ooff) {
    int r = (blockIdx.x * blockDim.x + threadIdx.x) >> 4;
    if (r >= nrows) return;
    pull_row(S, csr, wsrc, wdst, in, out, r, threadIdx.x & 15, ostride, ooff);
}

// ---------------------------------------------------------------------------
// FUSED: HAN attention (user+item, tensor cores) co-resident with gcn pull.
// ---------------------------------------------------------------------------
constexpr int WT_STRIDE = 72;

__global__ void gcn_attn_k(const float* __restrict__ ui_in, float* __restrict__ ui_out,
                           const float* __restrict__ W1u, const float* __restrict__ b1u,
                           const float* __restrict__ w2u,
                           const float* __restrict__ W1i, const float* __restrict__ b1i,
                           const float* __restrict__ w2i) {
    if (blockIdx.x >= GRID_ATTN) {
        // ---- gcn pull path ----
        int gid = (blockIdx.x - GRID_ATTN) * blockDim.x + threadIdx.x;
        int r = gid >> 4;
        if (r < N_N)
            pull_row(g_S + RB_GCN, g_csr, g_wdst + RB_GCN, g_wdst + RB_GCN,
                     ui_in, ui_out, r, gid & 15, 64, 0);
        return;
    }

    // ---- attention path ----
    bool isU = blockIdx.x < BLK_U;
    const float* z  = isU ? g_zu : g_zi;
    const float* W1 = isU ? W1u : W1i;
    const float* b1 = isU ? b1u : b1i;
    const float* w2 = isU ? w2u : w2i;
    int ntiles = isU ? NTU : NTI;
    int bid    = isU ? blockIdx.x : blockIdx.x - BLK_U;
    float* wsp = g_wsum + (isU ? 0 : 2);

    __shared__ __align__(16) __nv_bfloat16 Wt[HID * WT_STRIDE];
    __shared__ float b1s[HID];
    __shared__ float w2s[HID];
    __shared__ float r0s[256], r1s[256];

    for (int i = threadIdx.x; i < D * HID; i += blockDim.x) {
        int k = i >> 7, h = i & 127;
        Wt[h * WT_STRIDE + k] = __float2bfloat16(W1[i]);
    }
    if (threadIdx.x < HID) {
        b1s[threadIdx.x] = b1[threadIdx.x];
        w2s[threadIdx.x] = w2[threadIdx.x];
    }
    __syncthreads();

    int warp = threadIdx.x >> 5;
    int lane = threadIdx.x & 31;
    int g = lane >> 2;
    int tig = lane & 3;
    int tile = bid * 8 + warp;

    float acc0 = 0.f, acc1 = 0.f;

    if (tile < ntiles) {
        const float* zb = z + (size_t)tile * 16 * D;
        uint32_t A[4][4];
        #pragma unroll
        for (int kt = 0; kt < 4; kt++) {
            int k0 = kt * 16 + tig * 2;
            float2 v;
            v = *(const float2*)(zb + g * D + k0);            A[kt][0] = pack_bf16(v.x, v.y);
            v = *(const float2*)(zb + (g + 8) * D + k0);      A[kt][1] = pack_bf16(v.x, v.y);
            v = *(const float2*)(zb + g * D + k0 + 8);        A[kt][2] = pack_bf16(v.x, v.y);
            v = *(const float2*)(zb + (g + 8) * D + k0 + 8);  A[kt][3] = pack_bf16(v.x, v.y);
        }
        float s0 = 0.f, s1 = 0.f;
        #pragma unroll
        for (int nt = 0; nt < 16; nt++) {
            float c[4] = {0.f, 0.f, 0.f, 0.f};
            const __nv_bfloat16* wrow = Wt + (nt * 8 + g) * WT_STRIDE;
            #pragma unroll
            for (int kt = 0; kt < 4; kt++) {
                uint32_t b0 = *(const uint32_t*)(wrow + kt * 16 + tig * 2);
                uint32_t b1v = *(const uint32_t*)(wrow + kt * 16 + tig * 2 + 8);
                mma16816(c, A[kt], b0, b1v);
            }
            int col0 = nt * 8 + tig * 2;
            float bb0 = b1s[col0], bb1 = b1s[col0 + 1];
            float ww0 = w2s[col0], ww1 = w2s[col0 + 1];
            s0 = fmaf(tanh_fast(c[0] + bb0), ww0, s0);
            s0 = fmaf(tanh_fast(c[1] + bb1), ww1, s0);
            s1 = fmaf(tanh_fast(c[2] + bb0), ww0, s1);
            s1 = fmaf(tanh_fast(c[3] + bb1), ww1, s1);
        }
        s0 += __shfl_xor_sync(0xffffffffu, s0, 1);
        s0 += __shfl_xor_sync(0xffffffffu, s0, 2);
        s1 += __shfl_xor_sync(0xffffffffu, s1, 1);
        s1 += __shfl_xor_sync(0xffffffffu, s1, 2);
        if (tig == 0) {
            float v = s0 + s1;
            if (g & 1) acc1 += v; else acc0 += v;
        }
    }

    r0s[threadIdx.x] = acc0;
    r1s[threadIdx.x] = acc1;
    __syncthreads();
    for (int s = blockDim.x >> 1; s > 0; s >>= 1) {
        if (threadIdx.x < s) {
            r0s[threadIdx.x] += r0s[threadIdx.x + s];
            r1s[threadIdx.x] += r1s[threadIdx.x + s];
        }
        __syncthreads();
    }
    if (threadIdx.x == 0) {
        atomicAdd(&wsp[0], r0s[0]);
        atomicAdd(&wsp[1], r1s[0]);
    }
}

// both betas in one tiny launch
__global__ void beta2_k(const float* __restrict__ wsum, float* __restrict__ beta) {
    int t = threadIdx.x;
    if (t < 2) {
        float inv_n = (t == 0) ? (1.0f / U_N) : (1.0f / I_N);
        float a = wsum[2 * t] * inv_n;
        float b = wsum[2 * t + 1] * inv_n;
        float m = fmaxf(a, b);
        float e0 = expf(a - m), e1 = expf(b - m);
        float inv = 1.f / (e0 + e1);
        beta[2 * t]     = e0 * inv;
        beta[2 * t + 1] = e1 * inv;
    }
}

__global__ void zero_wsum_k(float* w) {
    if (threadIdx.x < 4) w[threadIdx.x] = 0.f;
}

// h[n,:] = beta0*z[n,0,:] + beta1*z[n,1,:]   (iteration 1 only)
__global__ void combine_k(const float* __restrict__ z, const float* __restrict__ beta,
                          float* __restrict__ h, int n) {
    int t = blockIdx.x * blockDim.x + threadIdx.x;
    if (t >= n * 16) return;
    int node = t >> 4;
    int c = t & 15;
    float b0 = beta[0], b1 = beta[1];
    float4 z0 = ((const float4*)z)[node * 32 + c];
    float4 z1 = ((const float4*)z)[node * 32 + 16 + c];
    float4 r;
    r.x = fmaf(b0, z0.x, b1 * z1.x);
    r.y = fmaf(b0, z0.y, b1 * z1.y);
    r.z = fmaf(b0, z0.z, b1 * z1.z);
    r.w = fmaf(b0, z0.w, b1 * z1.w);
    ((float4*)h)[t] = r;
}

// epilogue: iter-2 combine fused into the batched gathers
__global__ void out_k(const float* __restrict__ zu, const float* __restrict__ zi,
                      const float* __restrict__ ui, const float* __restrict__ beta,
                      const int* __restrict__ uidx, const int* __restrict__ iidx,
                      const int* __restrict__ nidx, float* __restrict__ out) {
    int t = blockIdx.x * blockDim.x + threadIdx.x;
    if (t >= B_N * 16) return;
    int b = t >> 4;
    int c = t & 15;
    const float4* zu4 = (const float4*)zu;
    const float4* zi4 = (const float4*)zi;
    const float4* ui4 = (const float4*)ui;
    float4* o4 = (float4*)out;
    float bU0 = beta[0], bU1 = beta[1], bI0 = beta[2], bI1 = beta[3];

    {
        int u = uidx[b];
        float4 z0 = zu4[u * 32 + c];
        float4 z1 = zu4[u * 32 + 16 + c];
        float4 g = ui4[u * 16 + c];
        float4 r;
        r.x = 0.5f * (fmaf(bU0, z0.x, bU1 * z1.x) + g.x);
        r.y = 0.5f * (fmaf(bU0, z0.y, bU1 * z1.y) + g.y);
        r.z = 0.5f * (fmaf(bU0, z0.z, bU1 * z1.z) + g.z);
        r.w = 0.5f * (fmaf(bU0, z0.w, bU1 * z1.w) + g.w);
        o4[t] = r;
    }
    {
        int it = iidx[b];
        float4 z0 = zi4[it * 32 + c];
        float4 z1 = zi4[it * 32 + 16 + c];
        float4 g = ui4[(U_N + it) * 16 + c];
        float4 r;
        r.x = 0.5f * (fmaf(bI0, z0.x, bI1 * z1.x) + g.x);
        r.y = 0.5f * (fmaf(bI0, z0.y, bI1 * z1.y) + g.y);
        r.z = 0.5f * (fmaf(bI0, z0.z, bI1 * z1.z) + g.z);
        r.w = 0.5f * (fmaf(bI0, z0.w, bI1 * z1.w) + g.w);
        o4[B_N * 16 + t] = r;
    }
    {
        int itn = iidx[nidx[b]];
        float4 z0 = zi4[itn * 32 + c];
        float4 z1 = zi4[itn * 32 + 16 + c];
        float4 g = ui4[(U_N + itn) * 16 + c];
        float4 r;
        r.x = 0.5f * (fmaf(bI0, z0.x, bI1 * z1.x) + g.x);
        r.y = 0.5f * (fmaf(bI0, z0.y, bI1 * z1.y) + g.y);
        r.z = 0.5f * (fmaf(bI0, z0.z, bI1 * z1.z) + g.z);
        r.w = 0.5f * (fmaf(bI0, z0.w, bI1 * z1.w) + g.w);
        o4[2 * B_N * 16 + t] = r;
    }
}

// ---------------------------------------------------------------------------
// Host
// ---------------------------------------------------------------------------
static inline int nblk(long long n) { return (int)((n + 255) / 256); }

extern "C" void kernel_launch(void* const* d_in, const int* in_sizes, int n_in,
                              void* d_out, int out_size) {
    const float* user_feat = (const float*)d_in[0];
    const float* item_feat = (const float*)d_in[1];
    const float* sa_u_W1   = (const float*)d_in[2];
    const float* sa_u_b1   = (const float*)d_in[3];
    const float* sa_u_w2   = (const float*)d_in[4];
    const float* sa_i_W1   = (const float*)d_in[5];
    const float* sa_i_b1   = (const float*)d_in[6];
    const float* sa_i_w2   = (const float*)d_in[7];
    const int*   ui_e      = (const int*)d_in[8];
    const int*   ue1       = (const int*)d_in[9];
    const int*   ue2       = (const int*)d_in[10];
    const int*   ie1       = (const int*)d_in[11];
    const int*   ie2       = (const int*)d_in[12];
    const int*   uidx      = (const int*)d_in[13];
    const int*   iidx      = (const int*)d_in[14];
    const int*   nidx      = (const int*)d_in[15];

    const int Eui = in_sizes[8]  / 2;   // 2,000,000
    const int Eu  = in_sizes[9]  / 2;   //   500,000
    const int Ei  = in_sizes[11] / 2;   // 1,000,000

    float *ui_a, *ui_b, *hu, *hi, *zu, *zi, *wsum, *beta;
    int *ibuf, *S, *csr;
    cudaGetSymbolAddress((void**)&ui_a, g_ui_a);
    cudaGetSymbolAddress((void**)&ui_b, g_ui_b);
    cudaGetSymbolAddress((void**)&hu,   g_hu);
    cudaGetSymbolAddress((void**)&hi,   g_hi);
    cudaGetSymbolAddress((void**)&zu,   g_zu);
    cudaGetSymbolAddress((void**)&zi,   g_zi);
    cudaGetSymbolAddress((void**)&wsum, g_wsum);
    cudaGetSymbolAddress((void**)&beta, g_beta);
    cudaGetSymbolAddress((void**)&ibuf, g_int);
    cudaGetSymbolAddress((void**)&S,    g_S);
    cudaGetSymbolAddress((void**)&csr,  g_csr);
    float *wdst, *wsrc;
    cudaGetSymbolAddress((void**)&wdst, g_wdst);
    cudaGetSymbolAddress((void**)&wsrc, g_wsrc);

    int* part = ibuf + OFF_PART;

    const int T = 256;

    // ---- zero int scratch (deg + dout + part; cursors overwritten by scan3w) ----
    zero_i4_k<<<nblk(INT_TOT / 4), T>>>((int4*)ibuf, INT_TOT / 4);

    // ---- init features ----
    init_k<<<nblk((long long)N_N * 16), T>>>((const float4*)user_feat,
                                             (const float4*)item_feat,
                                             (float4*)ui_a, (float4*)hu, (float4*)hi);

    // ---- fused degree counting (9 jobs, 4 edges/thread) ----
    CntJobs cj;
    const int* cp[9]  = {ui_e, ue1 + Eu, ue2 + Eu, ie1 + Ei, ie2 + Ei,
                         ue1, ue2, ie1, ie2};
    const int  ce[9]  = {Eui, Eu, Eu, Ei, Ei, Eu, Eu, Ei, Ei};
    const int  cd[9]  = {OFF_DEG + RB_GCN, OFF_DEG + RB_U1, OFF_DEG + RB_U2,
                         OFF_DEG + RB_I1, OFF_DEG + RB_I2,
                         OFF_DOUT + 0, OFF_DOUT + U_N,
                         OFF_DOUT + 2 * U_N, OFF_DOUT + 2 * U_N + I_N};
    {
        int acc = 0;
        for (int k = 0; k < 9; k++) {
            cj.ptr[k] = cp[k]; cj.dego[k] = cd[k]; cj.E[k] = ce[k];
            cj.qcum[k] = acc; acc += (ce[k] + 3) / 4;
        }
        cj.qcum[9] = acc;
        cnt_all_k<<<nblk(acc), T>>>(cj);
    }

    // ---- global exclusive scan -> CSR row offsets; cursor init; weights ----
    const int nchunks = (NSCAN + 2047) / 2048;  // 220
    scan1_k<<<nchunks, T>>>(ibuf + OFF_DEG, NSCAN, S, part);
    scan2_k<<<1, 256>>>(part, nchunks);
    scan3w_k<<<nblk(NSCAN), T>>>();

    // ---- fused CSR fill (5 jobs, 4 edges/thread, direct cursors) ----
    FillJobs fj;
    const int* fs[5] = {ui_e + Eui, ue1, ue2, ie1, ie2};
    const int* fd[5] = {ui_e, ue1 + Eu, ue2 + Eu, ie1 + Ei, ie2 + Ei};
    const int  fe[5] = {Eui, Eu, Eu, Ei, Ei};
    const int  fb[5] = {RB_GCN, RB_U1, RB_U2, RB_I1, RB_I2};
    {
        int acc = 0;
        for (int k = 0; k < 5; k++) {
            fj.src[k] = fs[k]; fj.dst[k] = fd[k]; fj.rb[k] = fb[k]; fj.E[k] = fe[k];
            fj.qcum[k] = acc; acc += (fe[k] + 3) / 4;
        }
        fj.qcum[5] = acc;
        fill_all_k<<<nblk(acc), T>>>(fj);
    }

    // ---- 2 propagation iterations ----
    const float* ui_in = ui_a;
    float* ui_out = ui_b;
    for (int iter = 0; iter < 2; ++iter) {
        // HAN metapath pulls (produce zu, zi)
        pull_k<<<nblk((long long)U_N * 16), T>>>(S + RB_U1, csr, wsrc + 0,
                                                 wdst + RB_U1, hu, zu, U_N, 128, 0);
        pull_k<<<nblk((long long)U_N * 16), T>>>(S + RB_U2, csr, wsrc + U_N,
                                                 wdst + RB_U2, hu, zu, U_N, 128, 64);
        pull_k<<<nblk((long long)I_N * 16), T>>>(S + RB_I1, csr, wsrc + 2 * U_N,
                                                 wdst + RB_I1, hi, zi, I_N, 128, 0);
        pull_k<<<nblk((long long)I_N * 16), T>>>(S + RB_I2, csr, wsrc + 2 * U_N + I_N,
                                                 wdst + RB_I2, hi, zi, I_N, 128, 64);

        zero_wsum_k<<<1, 32>>>(wsum);
        // fused: attention (zu/zi) co-resident with gcn pull (ui_in -> ui_out)
        gcn_attn_k<<<GRID_FUSE, 256>>>(ui_in, ui_out,
                                       sa_u_W1, sa_u_b1, sa_u_w2,
                                       sa_i_W1, sa_i_b1, sa_i_w2);
        beta2_k<<<1, 32>>>(wsum, beta);

        if (iter == 0) {
            combine_k<<<nblk((long long)U_N * 16), T>>>(zu, beta + 0, hu, U_N);
            combine_k<<<nblk((long long)I_N * 16), T>>>(zi, beta + 2, hi, I_N);
        }

        const float* tmp = ui_in;
        ui_in = ui_out;
        ui_out = (float*)tmp;
    }

    // ---- epilogue ----
    out_k<<<nblk((long long)B_N * 16), T>>>(zu, zi, ui_in, beta,
                                            uidx, iidx, nidx, (float*)d_out);
}

// round 10
// speedup vs baseline: 1.3201x; 1.0634x over previous
#include <cuda_runtime.h>
#include <cuda_bf16.h>
#include <cstdint>

// Problem constants (fixed by the dataset)
constexpr int U_N  = 50000;
constexpr int I_N  = 100000;
constexpr int N_N  = 150000;   // U + I
constexpr int D    = 64;
constexpr int B_N  = 8192;
constexpr int HID  = 128;

constexpr int NTOT  = N_N + 2 * U_N + 2 * I_N;   // 450000 CSR rows (5 graphs)
constexpr int NSCAN = NTOT + 1;
constexpr int E_TOT = 5000000;

// int scratch layout
constexpr int OFF_DEG  = 0;
constexpr int DEG_PAD  = 450008;
constexpr int OFF_CNT  = DEG_PAD;                // cursor array (init = S by scan23w)
constexpr int CNT_PAD  = 450008;
constexpr int OFF_DOUT = OFF_CNT + CNT_PAD;
constexpr int DOUT_LEN = 2 * U_N + 2 * I_N;      // 300000
constexpr int OFF_PART = OFF_DOUT + DOUT_LEN;
constexpr int INT_TOT  = OFF_PART + 256;

// CSR row bases within the concatenated degree/scan vector
constexpr int RB_GCN = 0;
constexpr int RB_U1  = N_N;
constexpr int RB_U2  = N_N + U_N;
constexpr int RB_I1  = N_N + 2 * U_N;
constexpr int RB_I2  = N_N + 2 * U_N + I_N;

// attention tiling (16-row tiles, 8 warps/block, one tile per warp)
constexpr int NTU   = (2 * U_N) / 16;            // 6250
constexpr int NTI   = (2 * I_N) / 16;            // 12500
constexpr int BLK_U = (NTU + 7) / 8;             // 782
constexpr int BLK_I = (NTI + 7) / 8;             // 1563
constexpr int GRID_ATTN = BLK_U + BLK_I;         // 2345
constexpr int GRID_GCN  = (N_N * 16) / 256;      // 9375
constexpr int GRID_FUSE = GRID_ATTN + GRID_GCN;  // 11720

constexpr int GRID_INIT = (N_N * 16) / 256;      // 9375 (init part of initcnt)

// ---------------------------------------------------------------------------
// Scratch (device globals: allocation-free)
// ---------------------------------------------------------------------------
__device__ __align__(256) float g_ui_a[N_N * D];
__device__ __align__(256) float g_ui_b[N_N * D];
__device__ __align__(256) float g_hu[U_N * D];
__device__ __align__(256) float g_hi[I_N * D];
__device__ __align__(256) float g_zu[U_N * 2 * D];
__device__ __align__(256) float g_zi[I_N * 2 * D];
__device__ __align__(256) float g_wdst[NTOT];
__device__ __align__(256) float g_wsrc[DOUT_LEN];
__device__ __align__(256) float g_wsum[4];
__device__ __align__(256) int   g_int[INT_TOT];
__device__ __align__(256) int   g_S[NSCAN + 8];
__device__ __align__(256) int   g_csr[E_TOT];

// ---------------------------------------------------------------------------
// Helpers
// ---------------------------------------------------------------------------
__device__ __forceinline__ float tanh_fast(float x) {
    float y;
    asm("tanh.approx.f32 %0, %1;" : "=f"(y) : "f"(x));
    return y;
}
__device__ __forceinline__ uint32_t pack_bf16(float lo, float hi) {
    uint32_t r;
    asm("cvt.rn.bf16x2.f32 %0, %1, %2;" : "=r"(r) : "f"(hi), "f"(lo));
    return r;
}
__device__ __forceinline__ void mma16816(float c[4], const uint32_t a[4],
                                         uint32_t b0, uint32_t b1) {
    asm volatile(
        "mma.sync.aligned.m16n8k16.row.col.f32.bf16.bf16.f32 "
        "{%0,%1,%2,%3}, {%4,%5,%6,%7}, {%8,%9}, {%0,%1,%2,%3};"
        : "+f"(c[0]), "+f"(c[1]), "+f"(c[2]), "+f"(c[3])
        : "r"(a[0]), "r"(a[1]), "r"(a[2]), "r"(a[3]), "r"(b0), "r"(b1));
}
// beta pair from wsum (user: off=0, inv=1/U; item: off=2, inv=1/I)
__device__ __forceinline__ float2 beta_pair(const float* __restrict__ wsum,
                                            int off, float inv_n) {
    float a = wsum[off] * inv_n;
    float b = wsum[off + 1] * inv_n;
    float m = fmaxf(a, b);
    float e0 = expf(a - m), e1 = expf(b - m);
    float inv = 1.f / (e0 + e1);
    return make_float2(e0 * inv, e1 * inv);
}

// ---------------------------------------------------------------------------
// Kernels
// ---------------------------------------------------------------------------
__global__ void zero_i4_k(int4* p, int n4) {
    int t = blockIdx.x * blockDim.x + threadIdx.x;
    if (t < n4) p[t] = make_int4(0, 0, 0, 0);
}

// ---------------------------------------------------------------------------
// FUSED init + degree counting: blocks [0, GRID_INIT) copy features,
// blocks [GRID_INIT, ...) count degrees (9 jobs, 4 edges/thread).
// The two are independent; init is store-BW-bound, cnt is atomic-bound.
// ---------------------------------------------------------------------------
struct CntJobs {
    const int* ptr[9];
    int        dego[9];   // offset into g_int
    int        E[9];      // edge counts
    int        qcum[10];  // cumulative quad-thread offsets
};

__global__ void initcnt_k(const float4* __restrict__ uf, const float4* __restrict__ itf,
                          CntJobs J) {
    if (blockIdx.x < GRID_INIT) {
        int t = blockIdx.x * blockDim.x + threadIdx.x;
        if (t < U_N * 16) {
            float4 v = uf[t];
            ((float4*)g_ui_a)[t] = v; ((float4*)g_hu)[t] = v;
        } else {
            float4 v = itf[t - U_N * 16];
            ((float4*)g_ui_a)[t] = v; ((float4*)g_hi)[t - U_N * 16] = v;
        }
        return;
    }
    int t = (blockIdx.x - GRID_INIT) * blockDim.x + threadIdx.x;
    if (t >= J.qcum[9]) return;
    int j = 0;
    #pragma unroll
    for (int k = 1; k < 9; k++) j += (t >= J.qcum[k]);
    int e0 = (t - J.qcum[j]) * 4;
    int E = J.E[j];
    const int* p = J.ptr[j];
    int* base = g_int + J.dego[j];
    #pragma unroll
    for (int i = 0; i < 4; i++) {
        int e = e0 + i;
        if (e < E) atomicAdd(&base[p[e]], 1);
    }
}

// --- scan phase 1: per-2048-chunk exclusive scan + chunk totals ---
__global__ void scan1_k(const int* __restrict__ deg, int n,
                        int* __restrict__ S, int* __restrict__ part) {
    __shared__ int warpsum[8];
    int base = blockIdx.x * 2048 + threadIdx.x * 8;
    int v[8];
    int s = 0;
    #pragma unroll
    for (int i = 0; i < 8; i++) {
        int x = (base + i < n) ? deg[base + i] : 0;
        v[i] = s; s += x;
    }
    int lane = threadIdx.x & 31, w = threadIdx.x >> 5;
    int ts = s;
    #pragma unroll
    for (int o = 1; o < 32; o <<= 1) {
        int y = __shfl_up_sync(0xffffffffu, ts, o);
        if (lane >= o) ts += y;
    }
    if (lane == 31) warpsum[w] = ts;
    __syncthreads();
    if (w == 0 && lane < 8) {
        int x = warpsum[lane];
        #pragma unroll
        for (int o = 1; o < 8; o <<= 1) {
            int y = __shfl_up_sync(0xffu, x, o);
            if (lane >= o) x += y;
        }
        warpsum[lane] = x;
    }
    __syncthreads();
    int prefix = (w > 0 ? warpsum[w - 1] : 0) + (ts - s);
    #pragma unroll
    for (int i = 0; i < 8; i++)
        if (base + i < n) S[base + i] = prefix + v[i];
    if (threadIdx.x == 0) part[blockIdx.x] = warpsum[7];
}

// --- scan phase 2+3 fused with cursor init + weights:
// each 2048-element block redundantly scans the 220 chunk totals in smem,
// adds its exclusive prefix, writes final S, cursor (=S), wdst, wsrc. ---
__global__ void scan23w_k(int nchunks) {
    __shared__ int sh[256];
    {
        int t = threadIdx.x;
        int x = (t < nchunks) ? g_int[OFF_PART + t] : 0;
        sh[t] = x;
        __syncthreads();
        for (int o = 1; o < 256; o <<= 1) {
            int y = (t >= o) ? sh[t - o] : 0;
            __syncthreads();
            sh[t] += y;
            __syncthreads();
        }
        // sh[c] = inclusive prefix; exclusive for chunk b is sh[b-1]
    }
    int psum = (blockIdx.x > 0) ? sh[blockIdx.x - 1] : 0;
    int base = blockIdx.x * 2048 + threadIdx.x * 8;
    #pragma unroll
    for (int i = 0; i < 8; i++) {
        int t = base + i;
        if (t >= NSCAN) break;
        int sv = g_S[t] + psum;
        g_S[t] = sv;
        if (t < NTOT) {
            g_int[OFF_CNT + t] = sv;   // fill cursor starts at row base
            float d = (float)g_int[OFF_DEG + t];
            g_wdst[t] = (t < N_N) ? ((d > 0.f) ? rsqrtf(d) : 0.f)
                                  : rsqrtf(fmaxf(d, 1.f));
        }
        if (t < DOUT_LEN)
            g_wsrc[t] = rsqrtf(fmaxf((float)g_int[OFF_DOUT + t], 1.f));
    }
}

// ---------------------------------------------------------------------------
// Fused CSR fill: 5 jobs, 4 edges per thread, direct global cursor
// ---------------------------------------------------------------------------
struct FillJobs {
    const int* src[5];
    const int* dst[5];
    int        rb[5];
    int        E[5];
    int        qcum[6];
};

__global__ void fill_all_k(FillJobs J) {
    int t = blockIdx.x * blockDim.x + threadIdx.x;
    if (t >= J.qcum[5]) return;
    int j = 0;
    #pragma unroll
    for (int k = 1; k < 5; k++) j += (t >= J.qcum[k]);
    int e0 = (t - J.qcum[j]) * 4;
    int E = J.E[j];
    const int* src = J.src[j];
    const int* dst = J.dst[j];
    int* cur = g_int + OFF_CNT + J.rb[j];
    #pragma unroll
    for (int i = 0; i < 4; i++) {
        int e = e0 + i;
        if (e < E) {
            int p = atomicAdd(&cur[dst[e]], 1);
            g_csr[p] = src[e];
        }
    }
}

// ---------------------------------------------------------------------------
// CSR pull SpMM body: half-warp per row, float4 payload (champion version)
// ---------------------------------------------------------------------------
__device__ __forceinline__ void pull_row(const int* __restrict__ S,
                                         const int* __restrict__ csr,
                                         const float* __restrict__ wsrc,
                                         const float* __restrict__ wdst,
                                         const float* __restrict__ in,
                                         float* __restrict__ out,
                                         int r, int lane, int ostride, int ooff) {
    int s = S[r], e = S[r + 1];
    float4 acc = make_float4(0.f, 0.f, 0.f, 0.f);
    int j = s;
    for (; j + 4 <= e; j += 4) {
        int c0 = csr[j], c1 = csr[j + 1], c2 = csr[j + 2], c3 = csr[j + 3];
        float w0 = wsrc[c0], w1 = wsrc[c1], w2 = wsrc[c2], w3 = wsrc[c3];
        float4 v0 = *(const float4*)(in + (size_t)c0 * D + lane * 4);
        float4 v1 = *(const float4*)(in + (size_t)c1 * D + lane * 4);
        float4 v2 = *(const float4*)(in + (size_t)c2 * D + lane * 4);
        float4 v3 = *(const float4*)(in + (size_t)c3 * D + lane * 4);
        acc.x = fmaf(w0, v0.x, acc.x); acc.y = fmaf(w0, v0.y, acc.y);
        acc.z = fmaf(w0, v0.z, acc.z); acc.w = fmaf(w0, v0.w, acc.w);
        acc.x = fmaf(w1, v1.x, acc.x); acc.y = fmaf(w1, v1.y, acc.y);
        acc.z = fmaf(w1, v1.z, acc.z); acc.w = fmaf(w1, v1.w, acc.w);
        acc.x = fmaf(w2, v2.x, acc.x); acc.y = fmaf(w2, v2.y, acc.y);
        acc.z = fmaf(w2, v2.z, acc.z); acc.w = fmaf(w2, v2.w, acc.w);
        acc.x = fmaf(w3, v3.x, acc.x); acc.y = fmaf(w3, v3.y, acc.y);
        acc.z = fmaf(w3, v3.z, acc.z); acc.w = fmaf(w3, v3.w, acc.w);
    }
    for (; j < e; j++) {
        int c = csr[j];
        float w = wsrc[c];
        float4 v = *(const float4*)(in + (size_t)c * D + lane * 4);
        acc.x = fmaf(w, v.x, acc.x); acc.y = fmaf(w, v.y, acc.y);
        acc.z = fmaf(w, v.z, acc.z); acc.w = fmaf(w, v.w, acc.w);
    }
    float wd = wdst[r];
    float4 o = make_float4(acc.x * wd, acc.y * wd, acc.z * wd, acc.w * wd);
    *(float4*)(out + (size_t)r * ostride + ooff + lane * 4) = o;
}

// ---------------------------------------------------------------------------
// Fused HAN pulls: all 4 metapath graphs in one grid (300K rows);
// also resets wsum for the following attention kernel.
// ---------------------------------------------------------------------------
__global__ void hanpull_k() {
    if (blockIdx.x == 0 && threadIdx.x < 4) g_wsum[threadIdx.x] = 0.f;
    int gr = (blockIdx.x * blockDim.x + threadIdx.x) >> 4;   // 0 .. 300K
    if (gr >= 2 * U_N + 2 * I_N) return;
    int lane = threadIdx.x & 15;
    int R = RB_U1 + gr;   // global CSR row

    const float* in;
    float* out;
    const float* ws;
    int ooff, lr;
    if (gr < U_N)              { in = g_hu; out = g_zu; ws = g_wsrc;               ooff = 0;  lr = gr; }
    else if (gr < 2 * U_N)     { in = g_hu; out = g_zu; ws = g_wsrc + U_N;         ooff = 64; lr = gr - U_N; }
    else if (gr < 2 * U_N + I_N) { in = g_hi; out = g_zi; ws = g_wsrc + 2 * U_N;   ooff = 0;  lr = gr - 2 * U_N; }
    else                       { in = g_hi; out = g_zi; ws = g_wsrc + 2 * U_N + I_N; ooff = 64; lr = gr - 2 * U_N - I_N; }

    // inline pull over global row R, local output row lr
    int s = g_S[R], e = g_S[R + 1];
    float4 acc = make_float4(0.f, 0.f, 0.f, 0.f);
    int j = s;
    for (; j + 4 <= e; j += 4) {
        int c0 = g_csr[j], c1 = g_csr[j + 1], c2 = g_csr[j + 2], c3 = g_csr[j + 3];
        float w0 = ws[c0], w1 = ws[c1], w2 = ws[c2], w3 = ws[c3];
        float4 v0 = *(const float4*)(in + (size_t)c0 * D + lane * 4);
        float4 v1 = *(const float4*)(in + (size_t)c1 * D + lane * 4);
        float4 v2 = *(const float4*)(in + (size_t)c2 * D + lane * 4);
        float4 v3 = *(const float4*)(in + (size_t)c3 * D + lane * 4);
        acc.x = fmaf(w0, v0.x, acc.x); acc.y = fmaf(w0, v0.y, acc.y);
        acc.z = fmaf(w0, v0.z, acc.z); acc.w = fmaf(w0, v0.w, acc.w);
        acc.x = fmaf(w1, v1.x, acc.x); acc.y = fmaf(w1, v1.y, acc.y);
        acc.z = fmaf(w1, v1.z, acc.z); acc.w = fmaf(w1, v1.w, acc.w);
        acc.x = fmaf(w2, v2.x, acc.x); acc.y = fmaf(w2, v2.y, acc.y);
        acc.z = fmaf(w2, v2.z, acc.z); acc.w = fmaf(w2, v2.w, acc.w);
        acc.x = fmaf(w3, v3.x, acc.x); acc.y = fmaf(w3, v3.y, acc.y);
        acc.z = fmaf(w3, v3.z, acc.z); acc.w = fmaf(w3, v3.w, acc.w);
    }
    for (; j < e; j++) {
        int c = g_csr[j];
        float w = ws[c];
        float4 v = *(const float4*)(in + (size_t)c * D + lane * 4);
        acc.x = fmaf(w, v.x, acc.x); acc.y = fmaf(w, v.y, acc.y);
        acc.z = fmaf(w, v.z, acc.z); acc.w = fmaf(w, v.w, acc.w);
    }
    float wd = g_wdst[R];
    float4 o = make_float4(acc.x * wd, acc.y * wd, acc.z * wd, acc.w * wd);
    *(float4*)(out + (size_t)lr * 128 + ooff + lane * 4) = o;
}

// ---------------------------------------------------------------------------
// FUSED: HAN attention (user+item, tensor cores) co-resident with gcn pull.
// ---------------------------------------------------------------------------
constexpr int WT_STRIDE = 72;

__global__ void gcn_attn_k(const float* __restrict__ ui_in, float* __restrict__ ui_out,
                           const float* __restrict__ W1u, const float* __restrict__ b1u,
                           const float* __restrict__ w2u,
                           const float* __restrict__ W1i, const float* __restrict__ b1i,
                           const float* __restrict__ w2i) {
    if (blockIdx.x >= GRID_ATTN) {
        // ---- gcn pull path ----
        int gid = (blockIdx.x - GRID_ATTN) * blockDim.x + threadIdx.x;
        int r = gid >> 4;
        if (r < N_N)
            pull_row(g_S + RB_GCN, g_csr, g_wdst + RB_GCN, g_wdst + RB_GCN,
                     ui_in, ui_out, r, gid & 15, 64, 0);
        return;
    }

    // ---- attention path ----
    bool isU = blockIdx.x < BLK_U;
    const float* z  = isU ? g_zu : g_zi;
    const float* W1 = isU ? W1u : W1i;
    const float* b1 = isU ? b1u : b1i;
    const float* w2 = isU ? w2u : w2i;
    int ntiles = isU ? NTU : NTI;
    int bid    = isU ? blockIdx.x : blockIdx.x - BLK_U;
    float* wsp = g_wsum + (isU ? 0 : 2);

    __shared__ __align__(16) __nv_bfloat16 Wt[HID * WT_STRIDE];
    __shared__ float b1s[HID];
    __shared__ float w2s[HID];
    __shared__ float r0s[256], r1s[256];

    for (int i = threadIdx.x; i < D * HID; i += blockDim.x) {
        int k = i >> 7, h = i & 127;
        Wt[h * WT_STRIDE + k] = __float2bfloat16(W1[i]);
    }
    if (threadIdx.x < HID) {
        b1s[threadIdx.x] = b1[threadIdx.x];
        w2s[threadIdx.x] = w2[threadIdx.x];
    }
    __syncthreads();

    int warp = threadIdx.x >> 5;
    int lane = threadIdx.x & 31;
    int g = lane >> 2;
    int tig = lane & 3;
    int tile = bid * 8 + warp;

    float acc0 = 0.f, acc1 = 0.f;

    if (tile < ntiles) {
        const float* zb = z + (size_t)tile * 16 * D;
        uint32_t A[4][4];
        #pragma unroll
        for (int kt = 0; kt < 4; kt++) {
            int k0 = kt * 16 + tig * 2;
            float2 v;
            v = *(const float2*)(zb + g * D + k0);            A[kt][0] = pack_bf16(v.x, v.y);
            v = *(const float2*)(zb + (g + 8) * D + k0);      A[kt][1] = pack_bf16(v.x, v.y);
            v = *(const float2*)(zb + g * D + k0 + 8);        A[kt][2] = pack_bf16(v.x, v.y);
            v = *(const float2*)(zb + (g + 8) * D + k0 + 8);  A[kt][3] = pack_bf16(v.x, v.y);
        }
        float s0 = 0.f, s1 = 0.f;
        #pragma unroll
        for (int nt = 0; nt < 16; nt++) {
            float c[4] = {0.f, 0.f, 0.f, 0.f};
            const __nv_bfloat16* wrow = Wt + (nt * 8 + g) * WT_STRIDE;
            #pragma unroll
            for (int kt = 0; kt < 4; kt++) {
                uint32_t b0 = *(const uint32_t*)(wrow + kt * 16 + tig * 2);
                uint32_t b1v = *(const uint32_t*)(wrow + kt * 16 + tig * 2 + 8);
                mma16816(c, A[kt], b0, b1v);
            }
            int col0 = nt * 8 + tig * 2;
            float bb0 = b1s[col0], bb1 = b1s[col0 + 1];
            float ww0 = w2s[col0], ww1 = w2s[col0 + 1];
            s0 = fmaf(tanh_fast(c[0] + bb0), ww0, s0);
            s0 = fmaf(tanh_fast(c[1] + bb1), ww1, s0);
            s1 = fmaf(tanh_fast(c[2] + bb0), ww0, s1);
            s1 = fmaf(tanh_fast(c[3] + bb1), ww1, s1);
        }
        s0 += __shfl_xor_sync(0xffffffffu, s0, 1);
        s0 += __shfl_xor_sync(0xffffffffu, s0, 2);
        s1 += __shfl_xor_sync(0xffffffffu, s1, 1);
        s1 += __shfl_xor_sync(0xffffffffu, s1, 2);
        if (tig == 0) {
            float v = s0 + s1;
            if (g & 1) acc1 += v; else acc0 += v;
        }
    }

    r0s[threadIdx.x] = acc0;
    r1s[threadIdx.x] = acc1;
    __syncthreads();
    for (int s = blockDim.x >> 1; s > 0; s >>= 1) {
        if (threadIdx.x < s) {
            r0s[threadIdx.x] += r0s[threadIdx.x + s];
            r1s[threadIdx.x] += r1s[threadIdx.x + s];
        }
        __syncthreads();
    }
    if (threadIdx.x == 0) {
        atomicAdd(&wsp[0], r0s[0]);
        atomicAdd(&wsp[1], r1s[0]);
    }
}

// ---------------------------------------------------------------------------
// Fused combine (user + item), beta computed inline from wsum:
// h = beta0*z[:,0,:] + beta1*z[:,1,:]   (iteration 1 only)
// ---------------------------------------------------------------------------
__global__ void combine_all_k() {
    int t = blockIdx.x * blockDim.x + threadIdx.x;
    if (t >= (U_N + I_N) * 16) return;
    int node = t >> 4;
    int c = t & 15;
    const float4* z;
    float4* h;
    float2 bb;
    if (node < U_N) {
        z = (const float4*)g_zu; h = (float4*)g_hu;
        bb = beta_pair(g_wsum, 0, 1.0f / U_N);
    } else {
        node -= U_N;
        z = (const float4*)g_zi; h = (float4*)g_hi;
        bb = beta_pair(g_wsum, 2, 1.0f / I_N);
    }
    float4 z0 = z[node * 32 + c];
    float4 z1 = z[node * 32 + 16 + c];
    float4 r;
    r.x = fmaf(bb.x, z0.x, bb.y * z1.x);
    r.y = fmaf(bb.x, z0.y, bb.y * z1.y);
    r.z = fmaf(bb.x, z0.z, bb.y * z1.z);
    r.w = fmaf(bb.x, z0.w, bb.y * z1.w);
    h[node * 16 + c] = r;
}

// epilogue: iter-2 combine fused into the batched gathers; beta inline
__global__ void out_k(const float* __restrict__ ui,
                      const int* __restrict__ uidx, const int* __restrict__ iidx,
                      const int* __restrict__ nidx, float* __restrict__ out) {
    int t = blockIdx.x * blockDim.x + threadIdx.x;
    if (t >= B_N * 16) return;
    int b = t >> 4;
    int c = t & 15;
    const float4* zu4 = (const float4*)g_zu;
    const float4* zi4 = (const float4*)g_zi;
    const float4* ui4 = (const float4*)ui;
    float4* o4 = (float4*)out;
    float2 bU = beta_pair(g_wsum, 0, 1.0f / U_N);
    float2 bI = beta_pair(g_wsum, 2, 1.0f / I_N);

    {
        int u = uidx[b];
        float4 z0 = zu4[u * 32 + c];
        float4 z1 = zu4[u * 32 + 16 + c];
        float4 g = ui4[u * 16 + c];
        float4 r;
        r.x = 0.5f * (fmaf(bU.x, z0.x, bU.y * z1.x) + g.x);
        r.y = 0.5f * (fmaf(bU.x, z0.y, bU.y * z1.y) + g.y);
        r.z = 0.5f * (fmaf(bU.x, z0.z, bU.y * z1.z) + g.z);
        r.w = 0.5f * (fmaf(bU.x, z0.w, bU.y * z1.w) + g.w);
        o4[t] = r;
    }
    {
        int it = iidx[b];
        float4 z0 = zi4[it * 32 + c];
        float4 z1 = zi4[it * 32 + 16 + c];
        float4 g = ui4[(U_N + it) * 16 + c];
        float4 r;
        r.x = 0.5f * (fmaf(bI.x, z0.x, bI.y * z1.x) + g.x);
        r.y = 0.5f * (fmaf(bI.x, z0.y, bI.y * z1.y) + g.y);
        r.z = 0.5f * (fmaf(bI.x, z0.z, bI.y * z1.z) + g.z);
        r.w = 0.5f * (fmaf(bI.x, z0.w, bI.y * z1.w) + g.w);
        o4[B_N * 16 + t] = r;
    }
    {
        int itn = iidx[nidx[b]];
        float4 z0 = zi4[itn * 32 + c];
        float4 z1 = zi4[itn * 32 + 16 + c];
        float4 g = ui4[(U_N + itn) * 16 + c];
        float4 r;
        r.x = 0.5f * (fmaf(bI.x, z0.x, bI.y * z1.x) + g.x);
        r.y = 0.5f * (fmaf(bI.x, z0.y, bI.y * z1.y) + g.y);
        r.z = 0.5f * (fmaf(bI.x, z0.z, bI.y * z1.z) + g.z);
        r.w = 0.5f * (fmaf(bI.x, z0.w, bI.y * z1.w) + g.w);
        o4[2 * B_N * 16 + t] = r;
    }
}

// ---------------------------------------------------------------------------
// Host
// ---------------------------------------------------------------------------
static inline int nblk(long long n) { return (int)((n + 255) / 256); }

extern "C" void kernel_launch(void* const* d_in, const int* in_sizes, int n_in,
                              void* d_out, int out_size) {
    const float* user_feat = (const float*)d_in[0];
    const float* item_feat = (const float*)d_in[1];
    const float* sa_u_W1   = (const float*)d_in[2];
    const float* sa_u_b1   = (const float*)d_in[3];
    const float* sa_u_w2   = (const float*)d_in[4];
    const float* sa_i_W1   = (const float*)d_in[5];
    const float* sa_i_b1   = (const float*)d_in[6];
    const float* sa_i_w2   = (const float*)d_in[7];
    const int*   ui_e      = (const int*)d_in[8];
    const int*   ue1       = (const int*)d_in[9];
    const int*   ue2       = (const int*)d_in[10];
    const int*   ie1       = (const int*)d_in[11];
    const int*   ie2       = (const int*)d_in[12];
    const int*   uidx      = (const int*)d_in[13];
    const int*   iidx      = (const int*)d_in[14];
    const int*   nidx      = (const int*)d_in[15];

    const int Eui = in_sizes[8]  / 2;   // 2,000,000
    const int Eu  = in_sizes[9]  / 2;   //   500,000
    const int Ei  = in_sizes[11] / 2;   // 1,000,000

    float *ui_a, *ui_b;
    int *ibuf, *S;
    cudaGetSymbolAddress((void**)&ui_a, g_ui_a);
    cudaGetSymbolAddress((void**)&ui_b, g_ui_b);
    cudaGetSymbolAddress((void**)&ibuf, g_int);
    cudaGetSymbolAddress((void**)&S,    g_S);

    const int T = 256;

    // ---- zero int scratch (deg + dout + part; cursors set by scan23w) ----
    zero_i4_k<<<nblk(INT_TOT / 4), T>>>((int4*)ibuf, INT_TOT / 4);

    // ---- fused init + degree counting ----
    CntJobs cj;
    const int* cp[9]  = {ui_e, ue1 + Eu, ue2 + Eu, ie1 + Ei, ie2 + Ei,
                         ue1, ue2, ie1, ie2};
    const int  ce[9]  = {Eui, Eu, Eu, Ei, Ei, Eu, Eu, Ei, Ei};
    const int  cd[9]  = {OFF_DEG + RB_GCN, OFF_DEG + RB_U1, OFF_DEG + RB_U2,
                         OFF_DEG + RB_I1, OFF_DEG + RB_I2,
                         OFF_DOUT + 0, OFF_DOUT + U_N,
                         OFF_DOUT + 2 * U_N, OFF_DOUT + 2 * U_N + I_N};
    {
        int acc = 0;
        for (int k = 0; k < 9; k++) {
            cj.ptr[k] = cp[k]; cj.dego[k] = cd[k]; cj.E[k] = ce[k];
            cj.qcum[k] = acc; acc += (ce[k] + 3) / 4;
        }
        cj.qcum[9] = acc;
        initcnt_k<<<GRID_INIT + nblk(acc), T>>>((const float4*)user_feat,
                                                (const float4*)item_feat, cj);
    }

    // ---- scan -> CSR row offsets; fused cursor init + weights ----
    const int nchunks = (NSCAN + 2047) / 2048;  // 220
    scan1_k<<<nchunks, T>>>(ibuf + OFF_DEG, NSCAN, S, ibuf + OFF_PART);
    scan23w_k<<<nchunks, 256>>>(nchunks);

    // ---- fused CSR fill (5 jobs, 4 edges/thread, direct cursors) ----
    FillJobs fj;
    const int* fs[5] = {ui_e + Eui, ue1, ue2, ie1, ie2};
    const int* fd[5] = {ui_e, ue1 + Eu, ue2 + Eu, ie1 + Ei, ie2 + Ei};
    const int  fe[5] = {Eui, Eu, Eu, Ei, Ei};
    const int  fb[5] = {RB_GCN, RB_U1, RB_U2, RB_I1, RB_I2};
    {
        int acc = 0;
        for (int k = 0; k < 5; k++) {
            fj.src[k] = fs[k]; fj.dst[k] = fd[k]; fj.rb[k] = fb[k]; fj.E[k] = fe[k];
            fj.qcum[k] = acc; acc += (fe[k] + 3) / 4;
        }
        fj.qcum[5] = acc;
        fill_all_k<<<nblk(acc), T>>>(fj);
    }

    // ---- 2 propagation iterations ----
    const float* ui_in = ui_a;
    float* ui_out = ui_b;
    for (int iter = 0; iter < 2; ++iter) {
        // fused HAN metapath pulls (produce zu, zi; reset wsum)
        hanpull_k<<<nblk((long long)(2 * U_N + 2 * I_N) * 16), T>>>();
        // fused: attention (zu/zi) co-resident with gcn pull (ui_in -> ui_out)
        gcn_attn_k<<<GRID_FUSE, 256>>>(ui_in, ui_out,
                                       sa_u_W1, sa_u_b1, sa_u_w2,
                                       sa_i_W1, sa_i_b1, sa_i_w2);
        if (iter == 0)
            combine_all_k<<<nblk((long long)(U_N + I_N) * 16), T>>>();
        const float* tmp = ui_in;
        ui_in = ui_out;
        ui_out = (float*)tmp;
    }

    // ---- epilogue ----
    out_k<<<nblk((long long)B_N * 16), T>>>(ui_in, uidx, iidx, nidx, (float*)d_out);
}

// round 11
// speedup vs baseline: 1.3363x; 1.0123x over previous
#include <cuda_runtime.h>
#include <cuda_bf16.h>
#include <cuda_fp16.h>
#include <cstdint>

// Problem constants (fixed by the dataset)
constexpr int U_N  = 50000;
constexpr int I_N  = 100000;
constexpr int N_N  = 150000;   // U + I
constexpr int D    = 64;
constexpr int B_N  = 8192;
constexpr int HID  = 128;

constexpr int NTOT  = N_N + 2 * U_N + 2 * I_N;   // 450000 CSR rows (5 graphs)
constexpr int NSCAN = NTOT + 1;
constexpr int E_TOT = 5000000;

// int scratch layout
constexpr int OFF_DEG  = 0;
constexpr int DEG_PAD  = 450008;
constexpr int OFF_CNT  = DEG_PAD;                // cursor array (init = S by scan23w)
constexpr int CNT_PAD  = 450008;
constexpr int OFF_DOUT = OFF_CNT + CNT_PAD;
constexpr int DOUT_LEN = 2 * U_N + 2 * I_N;      // 300000
constexpr int OFF_PART = OFF_DOUT + DOUT_LEN;
constexpr int INT_TOT  = OFF_PART + 256;

// CSR row bases within the concatenated degree/scan vector
constexpr int RB_GCN = 0;
constexpr int RB_U1  = N_N;
constexpr int RB_U2  = N_N + U_N;
constexpr int RB_I1  = N_N + 2 * U_N;
constexpr int RB_I2  = N_N + 2 * U_N + I_N;

// attention tiling (16-row tiles, 8 warps/block, one tile per warp)
constexpr int NTU   = (2 * U_N) / 16;            // 6250
constexpr int NTI   = (2 * I_N) / 16;            // 12500
constexpr int BLK_U = (NTU + 7) / 8;             // 782
constexpr int BLK_I = (NTI + 7) / 8;             // 1563
constexpr int GRID_ATTN = BLK_U + BLK_I;         // 2345
constexpr int GRID_GCN  = (N_N * 16) / 256;      // 9375
constexpr int GRID_FUSE = GRID_ATTN + GRID_GCN;  // 11720

constexpr int GRID_INIT = (N_N * 16) / 256;      // 9375 (init part of initcnt)

// ---------------------------------------------------------------------------
// Scratch (device globals: allocation-free)
// ---------------------------------------------------------------------------
__device__ __align__(256) __half g_ui16_a[N_N * D];   // fp16 gather ping
__device__ __align__(256) __half g_ui16_b[N_N * D];   // fp16 gather pong
__device__ __align__(256) float  g_ui32[N_N * D];     // fp32 final gcn output
__device__ __align__(256) __half g_hu16[U_N * D];
__device__ __align__(256) __half g_hi16[I_N * D];
__device__ __align__(256) float  g_zu[U_N * 2 * D];
__device__ __align__(256) float  g_zi[I_N * 2 * D];
__device__ __align__(256) float  g_wdst[NTOT];
__device__ __align__(256) float  g_wsrc[DOUT_LEN];
__device__ __align__(256) float  g_wsum[4];
__device__ __align__(256) int    g_int[INT_TOT];
__device__ __align__(256) int    g_S[NSCAN + 8];
__device__ __align__(256) int    g_csr[E_TOT];

// ---------------------------------------------------------------------------
// Helpers
// ---------------------------------------------------------------------------
__device__ __forceinline__ float tanh_fast(float x) {
    float y;
    asm("tanh.approx.f32 %0, %1;" : "=f"(y) : "f"(x));
    return y;
}
__device__ __forceinline__ uint32_t pack_bf16(float lo, float hi) {
    uint32_t r;
    asm("cvt.rn.bf16x2.f32 %0, %1, %2;" : "=r"(r) : "f"(hi), "f"(lo));
    return r;
}
__device__ __forceinline__ void mma16816(float c[4], const uint32_t a[4],
                                         uint32_t b0, uint32_t b1) {
    asm volatile(
        "mma.sync.aligned.m16n8k16.row.col.f32.bf16.bf16.f32 "
        "{%0,%1,%2,%3}, {%4,%5,%6,%7}, {%8,%9}, {%0,%1,%2,%3};"
        : "+f"(c[0]), "+f"(c[1]), "+f"(c[2]), "+f"(c[3])
        : "r"(a[0]), "r"(a[1]), "r"(a[2]), "r"(a[3]), "r"(b0), "r"(b1));
}
__device__ __forceinline__ float2 beta_pair(const float* __restrict__ wsum,
                                            int off, float inv_n) {
    float a = wsum[off] * inv_n;
    float b = wsum[off + 1] * inv_n;
    float m = fmaxf(a, b);
    float e0 = expf(a - m), e1 = expf(b - m);
    float inv = 1.f / (e0 + e1);
    return make_float2(e0 * inv, e1 * inv);
}
// load 4 consecutive halves (8B) from a row and accumulate w*val into acc
struct h4 { __half2 a, b; };
__device__ __forceinline__ void acc_h4(float4& acc, float w, const __half2* rowp, int lane) {
    h4 v = *(const h4*)(rowp + lane * 2);
    float2 f0 = __half22float2(v.a);
    float2 f1 = __half22float2(v.b);
    acc.x = fmaf(w, f0.x, acc.x);
    acc.y = fmaf(w, f0.y, acc.y);
    acc.z = fmaf(w, f1.x, acc.z);
    acc.w = fmaf(w, f1.y, acc.w);
}

// ---------------------------------------------------------------------------
// Kernels
// ---------------------------------------------------------------------------
__global__ void zero_i4_k(int4* p, int n4) {
    int t = blockIdx.x * blockDim.x + threadIdx.x;
    if (t < n4) p[t] = make_int4(0, 0, 0, 0);
}

// ---------------------------------------------------------------------------
// FUSED init + degree counting: blocks [0, GRID_INIT) convert features to
// fp16 (ui ping + hu/hi), blocks [GRID_INIT, ...) count degrees.
// ---------------------------------------------------------------------------
struct CntJobs {
    const int* ptr[9];
    int        dego[9];
    int        E[9];
    int        qcum[10];
};

__global__ void initcnt_k(const float4* __restrict__ uf, const float4* __restrict__ itf,
                          CntJobs J) {
    if (blockIdx.x < GRID_INIT) {
        int t = blockIdx.x * blockDim.x + threadIdx.x;   // handles 4 floats
        float4 v;
        __half2* hdst;
        int hidx;
        if (t < U_N * 16) {
            v = uf[t];
            hdst = (__half2*)g_hu16; hidx = 2 * t;
        } else {
            v = itf[t - U_N * 16];
            hdst = (__half2*)g_hi16; hidx = 2 * (t - U_N * 16);
        }
        __half2 h0 = __floats2half2_rn(v.x, v.y);
        __half2 h1 = __floats2half2_rn(v.z, v.w);
        ((__half2*)g_ui16_a)[2 * t]     = h0;
        ((__half2*)g_ui16_a)[2 * t + 1] = h1;
        hdst[hidx]     = h0;
        hdst[hidx + 1] = h1;
        return;
    }
    int t = (blockIdx.x - GRID_INIT) * blockDim.x + threadIdx.x;
    if (t >= J.qcum[9]) return;
    int j = 0;
    #pragma unroll
    for (int k = 1; k < 9; k++) j += (t >= J.qcum[k]);
    int e0 = (t - J.qcum[j]) * 4;
    int E = J.E[j];
    const int* p = J.ptr[j];
    int* base = g_int + J.dego[j];
    #pragma unroll
    for (int i = 0; i < 4; i++) {
        int e = e0 + i;
        if (e < E) atomicAdd(&base[p[e]], 1);
    }
}

// --- scan phase 1: per-2048-chunk exclusive scan + chunk totals ---
__global__ void scan1_k(const int* __restrict__ deg, int n,
                        int* __restrict__ S, int* __restrict__ part) {
    __shared__ int warpsum[8];
    int base = blockIdx.x * 2048 + threadIdx.x * 8;
    int v[8];
    int s = 0;
    #pragma unroll
    for (int i = 0; i < 8; i++) {
        int x = (base + i < n) ? deg[base + i] : 0;
        v[i] = s; s += x;
    }
    int lane = threadIdx.x & 31, w = threadIdx.x >> 5;
    int ts = s;
    #pragma unroll
    for (int o = 1; o < 32; o <<= 1) {
        int y = __shfl_up_sync(0xffffffffu, ts, o);
        if (lane >= o) ts += y;
    }
    if (lane == 31) warpsum[w] = ts;
    __syncthreads();
    if (w == 0 && lane < 8) {
        int x = warpsum[lane];
        #pragma unroll
        for (int o = 1; o < 8; o <<= 1) {
            int y = __shfl_up_sync(0xffu, x, o);
            if (lane >= o) x += y;
        }
        warpsum[lane] = x;
    }
    __syncthreads();
    int prefix = (w > 0 ? warpsum[w - 1] : 0) + (ts - s);
    #pragma unroll
    for (int i = 0; i < 8; i++)
        if (base + i < n) S[base + i] = prefix + v[i];
    if (threadIdx.x == 0) part[blockIdx.x] = warpsum[7];
}

// --- scan phase 2+3 fused with cursor init + weights ---
__global__ void scan23w_k(int nchunks) {
    __shared__ int sh[256];
    {
        int t = threadIdx.x;
        int x = (t < nchunks) ? g_int[OFF_PART + t] : 0;
        sh[t] = x;
        __syncthreads();
        for (int o = 1; o < 256; o <<= 1) {
            int y = (t >= o) ? sh[t - o] : 0;
            __syncthreads();
            sh[t] += y;
            __syncthreads();
        }
    }
    int psum = (blockIdx.x > 0) ? sh[blockIdx.x - 1] : 0;
    int base = blockIdx.x * 2048 + threadIdx.x * 8;
    #pragma unroll
    for (int i = 0; i < 8; i++) {
        int t = base + i;
        if (t >= NSCAN) break;
        int sv = g_S[t] + psum;
        g_S[t] = sv;
        if (t < NTOT) {
            g_int[OFF_CNT + t] = sv;
            float d = (float)g_int[OFF_DEG + t];
            g_wdst[t] = (t < N_N) ? ((d > 0.f) ? rsqrtf(d) : 0.f)
                                  : rsqrtf(fmaxf(d, 1.f));
        }
        if (t < DOUT_LEN)
            g_wsrc[t] = rsqrtf(fmaxf((float)g_int[OFF_DOUT + t], 1.f));
    }
}

// ---------------------------------------------------------------------------
// Fused CSR fill: 5 jobs, 4 edges per thread, direct global cursor
// ---------------------------------------------------------------------------
struct FillJobs {
    const int* src[5];
    const int* dst[5];
    int        rb[5];
    int        E[5];
    int        qcum[6];
};

__global__ void fill_all_k(FillJobs J) {
    int t = blockIdx.x * blockDim.x + threadIdx.x;
    if (t >= J.qcum[5]) return;
    int j = 0;
    #pragma unroll
    for (int k = 1; k < 5; k++) j += (t >= J.qcum[k]);
    int e0 = (t - J.qcum[j]) * 4;
    int E = J.E[j];
    const int* src = J.src[j];
    const int* dst = J.dst[j];
    int* cur = g_int + OFF_CNT + J.rb[j];
    #pragma unroll
    for (int i = 0; i < 4; i++) {
        int e = e0 + i;
        if (e < E) {
            int p = atomicAdd(&cur[dst[e]], 1);
            g_csr[p] = src[e];
        }
    }
}

// ---------------------------------------------------------------------------
// fp16 CSR pull body: half-warp per row, 128B/edge (one L2 line), fp32 accum.
// Returns the scaled accumulator (4 output floats for this lane).
// ---------------------------------------------------------------------------
__device__ __forceinline__ float4 pull_row16(const int* __restrict__ S,
                                             const int* __restrict__ csr,
                                             const float* __restrict__ wsrc,
                                             const float* __restrict__ wdst,
                                             const __half2* __restrict__ in,  // row stride 32 half2
                                             int r, int lane) {
    int s = S[r], e = S[r + 1];
    float4 acc = make_float4(0.f, 0.f, 0.f, 0.f);
    int j = s;
    for (; j + 4 <= e; j += 4) {
        int c0 = csr[j], c1 = csr[j + 1], c2 = csr[j + 2], c3 = csr[j + 3];
        float w0 = wsrc[c0], w1 = wsrc[c1], w2 = wsrc[c2], w3 = wsrc[c3];
        acc_h4(acc, w0, in + (size_t)c0 * 32, lane);
        acc_h4(acc, w1, in + (size_t)c1 * 32, lane);
        acc_h4(acc, w2, in + (size_t)c2 * 32, lane);
        acc_h4(acc, w3, in + (size_t)c3 * 32, lane);
    }
    for (; j < e; j++) {
        int c = csr[j];
        acc_h4(acc, wsrc[c], in + (size_t)c * 32, lane);
    }
    float wd = wdst[r];
    return make_float4(acc.x * wd, acc.y * wd, acc.z * wd, acc.w * wd);
}

// ---------------------------------------------------------------------------
// Fused HAN pulls: all 4 metapath graphs in one grid (300K rows), fp16 in,
// fp32 z out; also resets wsum for the following attention kernel.
// ---------------------------------------------------------------------------
__global__ void hanpull_k() {
    if (blockIdx.x == 0 && threadIdx.x < 4) g_wsum[threadIdx.x] = 0.f;
    int gr = (blockIdx.x * blockDim.x + threadIdx.x) >> 4;   // 0 .. 300K
    if (gr >= 2 * U_N + 2 * I_N) return;
    int lane = threadIdx.x & 15;
    int R = RB_U1 + gr;

    const __half2* in;
    float* out;
    const float* ws;
    int ooff, lr;
    if (gr < U_N)                { in = (const __half2*)g_hu16; out = g_zu; ws = g_wsrc;               ooff = 0;  lr = gr; }
    else if (gr < 2 * U_N)       { in = (const __half2*)g_hu16; out = g_zu; ws = g_wsrc + U_N;         ooff = 64; lr = gr - U_N; }
    else if (gr < 2 * U_N + I_N) { in = (const __half2*)g_hi16; out = g_zi; ws = g_wsrc + 2 * U_N;     ooff = 0;  lr = gr - 2 * U_N; }
    else                         { in = (const __half2*)g_hi16; out = g_zi; ws = g_wsrc + 2 * U_N + I_N; ooff = 64; lr = gr - 2 * U_N - I_N; }

    float4 o = pull_row16(g_S, g_csr, ws, g_wdst, in, R, lane);
    *(float4*)(out + (size_t)lr * 128 + ooff + lane * 4) = o;
}

// ---------------------------------------------------------------------------
// FUSED: HAN attention (user+item, tensor cores) co-resident with gcn pull.
// gcn pull: fp16 in; iter0 writes fp16 pong, iter1 writes fp32 g_ui32.
// ---------------------------------------------------------------------------
constexpr int WT_STRIDE = 72;

__global__ void gcn_attn_k(const __half2* __restrict__ ui_in16,
                           __half2* __restrict__ ui_out16,
                           float* __restrict__ ui_out32, int last,
                           const float* __restrict__ W1u, const float* __restrict__ b1u,
                           const float* __restrict__ w2u,
                           const float* __restrict__ W1i, const float* __restrict__ b1i,
                           const float* __restrict__ w2i) {
    if (blockIdx.x >= GRID_ATTN) {
        // ---- gcn pull path ----
        int gid = (blockIdx.x - GRID_ATTN) * blockDim.x + threadIdx.x;
        int r = gid >> 4;
        if (r < N_N) {
            int lane = gid & 15;
            float4 o = pull_row16(g_S + RB_GCN, g_csr, g_wdst + RB_GCN,
                                  g_wdst + RB_GCN, ui_in16, r, lane);
            if (last) {
                *(float4*)(ui_out32 + (size_t)r * D + lane * 4) = o;
            } else {
                h4 hv;
                hv.a = __floats2half2_rn(o.x, o.y);
                hv.b = __floats2half2_rn(o.z, o.w);
                *(h4*)(ui_out16 + (size_t)r * 32 + lane * 2) = hv;
            }
        }
        return;
    }

    // ---- attention path (fp32 zu/zi, unchanged) ----
    bool isU = blockIdx.x < BLK_U;
    const float* z  = isU ? g_zu : g_zi;
    const float* W1 = isU ? W1u : W1i;
    const float* b1 = isU ? b1u : b1i;
    const float* w2 = isU ? w2u : w2i;
    int ntiles = isU ? NTU : NTI;
    int bid    = isU ? blockIdx.x : blockIdx.x - BLK_U;
    float* wsp = g_wsum + (isU ? 0 : 2);

    __shared__ __align__(16) __nv_bfloat16 Wt[HID * WT_STRIDE];
    __shared__ float b1s[HID];
    __shared__ float w2s[HID];
    __shared__ float r0s[256], r1s[256];

    for (int i = threadIdx.x; i < D * HID; i += blockDim.x) {
        int k = i >> 7, h = i & 127;
        Wt[h * WT_STRIDE + k] = __float2bfloat16(W1[i]);
    }
    if (threadIdx.x < HID) {
        b1s[threadIdx.x] = b1[threadIdx.x];
        w2s[threadIdx.x] = w2[threadIdx.x];
    }
    __syncthreads();

    int warp = threadIdx.x >> 5;
    int lane = threadIdx.x & 31;
    int g = lane >> 2;
    int tig = lane & 3;
    int tile = bid * 8 + warp;

    float acc0 = 0.f, acc1 = 0.f;

    if (tile < ntiles) {
        const float* zb = z + (size_t)tile * 16 * D;
        uint32_t A[4][4];
        #pragma unroll
        for (int kt = 0; kt < 4; kt++) {
            int k0 = kt * 16 + tig * 2;
            float2 v;
            v = *(const float2*)(zb + g * D + k0);            A[kt][0] = pack_bf16(v.x, v.y);
            v = *(const float2*)(zb + (g + 8) * D + k0);      A[kt][1] = pack_bf16(v.x, v.y);
            v = *(const float2*)(zb + g * D + k0 + 8);        A[kt][2] = pack_bf16(v.x, v.y);
            v = *(const float2*)(zb + (g + 8) * D + k0 + 8);  A[kt][3] = pack_bf16(v.x, v.y);
        }
        float s0 = 0.f, s1 = 0.f;
        #pragma unroll
        for (int nt = 0; nt < 16; nt++) {
            float c[4] = {0.f, 0.f, 0.f, 0.f};
            const __nv_bfloat16* wrow = Wt + (nt * 8 + g) * WT_STRIDE;
            #pragma unroll
            for (int kt = 0; kt < 4; kt++) {
                uint32_t b0 = *(const uint32_t*)(wrow + kt * 16 + tig * 2);
                uint32_t b1v = *(const uint32_t*)(wrow + kt * 16 + tig * 2 + 8);
                mma16816(c, A[kt], b0, b1v);
            }
            int col0 = nt * 8 + tig * 2;
            float bb0 = b1s[col0], bb1 = b1s[col0 + 1];
            float ww0 = w2s[col0], ww1 = w2s[col0 + 1];
            s0 = fmaf(tanh_fast(c[0] + bb0), ww0, s0);
            s0 = fmaf(tanh_fast(c[1] + bb1), ww1, s0);
            s1 = fmaf(tanh_fast(c[2] + bb0), ww0, s1);
            s1 = fmaf(tanh_fast(c[3] + bb1), ww1, s1);
        }
        s0 += __shfl_xor_sync(0xffffffffu, s0, 1);
        s0 += __shfl_xor_sync(0xffffffffu, s0, 2);
        s1 += __shfl_xor_sync(0xffffffffu, s1, 1);
        s1 += __shfl_xor_sync(0xffffffffu, s1, 2);
        if (tig == 0) {
            float v = s0 + s1;
            if (g & 1) acc1 += v; else acc0 += v;
        }
    }

    r0s[threadIdx.x] = acc0;
    r1s[threadIdx.x] = acc1;
    __syncthreads();
    for (int s = blockDim.x >> 1; s > 0; s >>= 1) {
        if (threadIdx.x < s) {
            r0s[threadIdx.x] += r0s[threadIdx.x + s];
            r1s[threadIdx.x] += r1s[threadIdx.x + s];
        }
        __syncthreads();
    }
    if (threadIdx.x == 0) {
        atomicAdd(&wsp[0], r0s[0]);
        atomicAdd(&wsp[1], r1s[0]);
    }
}

// ---------------------------------------------------------------------------
// Fused combine (user + item), beta inline; writes fp16 h (iteration 1 only)
// ---------------------------------------------------------------------------
__global__ void combine_all_k() {
    int t = blockIdx.x * blockDim.x + threadIdx.x;
    if (t >= (U_N + I_N) * 16) return;
    int node = t >> 4;
    int c = t & 15;
    const float4* z;
    __half2* h;
    float2 bb;
    if (node < U_N) {
        z = (const float4*)g_zu; h = (__half2*)g_hu16;
        bb = beta_pair(g_wsum, 0, 1.0f / U_N);
    } else {
        node -= U_N;
        z = (const float4*)g_zi; h = (__half2*)g_hi16;
        bb = beta_pair(g_wsum, 2, 1.0f / I_N);
    }
    float4 z0 = z[node * 32 + c];
    float4 z1 = z[node * 32 + 16 + c];
    float rx = fmaf(bb.x, z0.x, bb.y * z1.x);
    float ry = fmaf(bb.x, z0.y, bb.y * z1.y);
    float rz = fmaf(bb.x, z0.z, bb.y * z1.z);
    float rw = fmaf(bb.x, z0.w, bb.y * z1.w);
    h[node * 32 + c * 2]     = __floats2half2_rn(rx, ry);
    h[node * 32 + c * 2 + 1] = __floats2half2_rn(rz, rw);
}

// epilogue: iter-2 combine fused into the batched gathers; beta inline
__global__ void out_k(const int* __restrict__ uidx, const int* __restrict__ iidx,
                      const int* __restrict__ nidx, float* __restrict__ out) {
    int t = blockIdx.x * blockDim.x + threadIdx.x;
    if (t >= B_N * 16) return;
    int b = t >> 4;
    int c = t & 15;
    const float4* zu4 = (const float4*)g_zu;
    const float4* zi4 = (const float4*)g_zi;
    const float4* ui4 = (const float4*)g_ui32;
    float4* o4 = (float4*)out;
    float2 bU = beta_pair(g_wsum, 0, 1.0f / U_N);
    float2 bI = beta_pair(g_wsum, 2, 1.0f / I_N);

    {
        int u = uidx[b];
        float4 z0 = zu4[u * 32 + c];
        float4 z1 = zu4[u * 32 + 16 + c];
        float4 g = ui4[u * 16 + c];
        float4 r;
        r.x = 0.5f * (fmaf(bU.x, z0.x, bU.y * z1.x) + g.x);
        r.y = 0.5f * (fmaf(bU.x, z0.y, bU.y * z1.y) + g.y);
        r.z = 0.5f * (fmaf(bU.x, z0.z, bU.y * z1.z) + g.z);
        r.w = 0.5f * (fmaf(bU.x, z0.w, bU.y * z1.w) + g.w);
        o4[t] = r;
    }
    {
        int it = iidx[b];
        float4 z0 = zi4[it * 32 + c];
        float4 z1 = zi4[it * 32 + 16 + c];
        float4 g = ui4[(U_N + it) * 16 + c];
        float4 r;
        r.x = 0.5f * (fmaf(bI.x, z0.x, bI.y * z1.x) + g.x);
        r.y = 0.5f * (fmaf(bI.x, z0.y, bI.y * z1.y) + g.y);
        r.z = 0.5f * (fmaf(bI.x, z0.z, bI.y * z1.z) + g.z);
        r.w = 0.5f * (fmaf(bI.x, z0.w, bI.y * z1.w) + g.w);
        o4[B_N * 16 + t] = r;
    }
    {
        int itn = iidx[nidx[b]];
        float4 z0 = zi4[itn * 32 + c];
        float4 z1 = zi4[itn * 32 + 16 + c];
        float4 g = ui4[(U_N + itn) * 16 + c];
        float4 r;
        r.x = 0.5f * (fmaf(bI.x, z0.x, bI.y * z1.x) + g.x);
        r.y = 0.5f * (fmaf(bI.x, z0.y, bI.y * z1.y) + g.y);
        r.z = 0.5f * (fmaf(bI.x, z0.z, bI.y * z1.z) + g.z);
        r.w = 0.5f * (fmaf(bI.x, z0.w, bI.y * z1.w) + g.w);
        o4[2 * B_N * 16 + t] = r;
    }
}

// ---------------------------------------------------------------------------
// Host
// ---------------------------------------------------------------------------
static inline int nblk(long long n) { return (int)((n + 255) / 256); }

extern "C" void kernel_launch(void* const* d_in, const int* in_sizes, int n_in,
                              void* d_out, int out_size) {
    const float* user_feat = (const float*)d_in[0];
    const float* item_feat = (const float*)d_in[1];
    const float* sa_u_W1   = (const float*)d_in[2];
    const float* sa_u_b1   = (const float*)d_in[3];
    const float* sa_u_w2   = (const float*)d_in[4];
    const float* sa_i_W1   = (const float*)d_in[5];
    const float* sa_i_b1   = (const float*)d_in[6];
    const float* sa_i_w2   = (const float*)d_in[7];
    const int*   ui_e      = (const int*)d_in[8];
    const int*   ue1       = (const int*)d_in[9];
    const int*   ue2       = (const int*)d_in[10];
    const int*   ie1       = (const int*)d_in[11];
    const int*   ie2       = (const int*)d_in[12];
    const int*   uidx      = (const int*)d_in[13];
    const int*   iidx      = (const int*)d_in[14];
    const int*   nidx      = (const int*)d_in[15];

    const int Eui = in_sizes[8]  / 2;   // 2,000,000
    const int Eu  = in_sizes[9]  / 2;   //   500,000
    const int Ei  = in_sizes[11] / 2;   // 1,000,000

    __half *ui16_a, *ui16_b;
    float* ui32;
    int *ibuf, *S;
    cudaGetSymbolAddress((void**)&ui16_a, g_ui16_a);
    cudaGetSymbolAddress((void**)&ui16_b, g_ui16_b);
    cudaGetSymbolAddress((void**)&ui32,   g_ui32);
    cudaGetSymbolAddress((void**)&ibuf,   g_int);
    cudaGetSymbolAddress((void**)&S,      g_S);

    const int T = 256;

    // ---- zero int scratch ----
    zero_i4_k<<<nblk(INT_TOT / 4), T>>>((int4*)ibuf, INT_TOT / 4);

    // ---- fused init + degree counting ----
    CntJobs cj;
    const int* cp[9]  = {ui_e, ue1 + Eu, ue2 + Eu, ie1 + Ei, ie2 + Ei,
                         ue1, ue2, ie1, ie2};
    const int  ce[9]  = {Eui, Eu, Eu, Ei, Ei, Eu, Eu, Ei, Ei};
    const int  cd[9]  = {OFF_DEG + RB_GCN, OFF_DEG + RB_U1, OFF_DEG + RB_U2,
                         OFF_DEG + RB_I1, OFF_DEG + RB_I2,
                         OFF_DOUT + 0, OFF_DOUT + U_N,
                         OFF_DOUT + 2 * U_N, OFF_DOUT + 2 * U_N + I_N};
    {
        int acc = 0;
        for (int k = 0; k < 9; k++) {
            cj.ptr[k] = cp[k]; cj.dego[k] = cd[k]; cj.E[k] = ce[k];
            cj.qcum[k] = acc; acc += (ce[k] + 3) / 4;
        }
        cj.qcum[9] = acc;
        initcnt_k<<<GRID_INIT + nblk(acc), T>>>((const float4*)user_feat,
                                                (const float4*)item_feat, cj);
    }

    // ---- scan -> CSR row offsets; fused cursor init + weights ----
    const int nchunks = (NSCAN + 2047) / 2048;  // 220
    scan1_k<<<nchunks, T>>>(ibuf + OFF_DEG, NSCAN, S, ibuf + OFF_PART);
    scan23w_k<<<nchunks, 256>>>(nchunks);

    // ---- fused CSR fill ----
    FillJobs fj;
    const int* fs[5] = {ui_e + Eui, ue1, ue2, ie1, ie2};
    const int* fd[5] = {ui_e, ue1 + Eu, ue2 + Eu, ie1 + Ei, ie2 + Ei};
    const int  fe[5] = {Eui, Eu, Eu, Ei, Ei};
    const int  fb[5] = {RB_GCN, RB_U1, RB_U2, RB_I1, RB_I2};
    {
        int acc = 0;
        for (int k = 0; k < 5; k++) {
            fj.src[k] = fs[k]; fj.dst[k] = fd[k]; fj.rb[k] = fb[k]; fj.E[k] = fe[k];
            fj.qcum[k] = acc; acc += (fe[k] + 3) / 4;
        }
        fj.qcum[5] = acc;
        fill_all_k<<<nblk(acc), T>>>(fj);
    }

    // ---- 2 propagation iterations ----
    // iter 0: gcn gathers ui16_a -> ui16_b (fp16); combine writes fp16 h
    hanpull_k<<<nblk((long long)(2 * U_N + 2 * I_N) * 16), T>>>();
    gcn_attn_k<<<GRID_FUSE, 256>>>((const __half2*)ui16_a, (__half2*)ui16_b,
                                   nullptr, 0,
                                   sa_u_W1, sa_u_b1, sa_u_w2,
                                   sa_i_W1, sa_i_b1, sa_i_w2);
    combine_all_k<<<nblk((long long)(U_N + I_N) * 16), T>>>();

    // iter 1: gcn gathers ui16_b -> ui32 (fp32 epilogue source)
    hanpull_k<<<nblk((long long)(2 * U_N + 2 * I_N) * 16), T>>>();
    gcn_attn_k<<<GRID_FUSE, 256>>>((const __half2*)ui16_b, nullptr,
                                   ui32, 1,
                                   sa_u_W1, sa_u_b1, sa_u_w2,
                                   sa_i_W1, sa_i_b1, sa_i_w2);

    // ---- epilogue ----
    out_k<<<nblk((long long)B_N * 16), T>>>(uidx, iidx, nidx, (float*)d_out);
}

// round 13
// speedup vs baseline: 1.5042x; 1.1256x over previous
#include <cuda_runtime.h>
#include <cuda_bf16.h>
#include <cuda_fp16.h>
#include <cstdint>

// Problem constants (fixed by the dataset)
constexpr int U_N  = 50000;
constexpr int I_N  = 100000;
constexpr int N_N  = 150000;   // U + I
constexpr int D    = 64;
constexpr int B_N  = 8192;
constexpr int HID  = 128;

constexpr int NTOT  = N_N + 2 * U_N + 2 * I_N;   // 450000 CSR rows (5 graphs)
constexpr int NSCAN = NTOT + 1;
constexpr int E_TOT = 5000000;

// int scratch layout
constexpr int OFF_DEG  = 0;
constexpr int DEG_PAD  = 450008;
constexpr int OFF_CNT  = DEG_PAD;                // cursor array (init = S by scan23w)
constexpr int CNT_PAD  = 450008;
constexpr int OFF_DOUT = OFF_CNT + CNT_PAD;
constexpr int DOUT_LEN = 2 * U_N + 2 * I_N;      // 300000
constexpr int OFF_PART = OFF_DOUT + DOUT_LEN;
constexpr int INT_TOT  = OFF_PART + 256;

// CSR row bases within the concatenated degree/scan vector
constexpr int RB_GCN = 0;
constexpr int RB_U1  = N_N;
constexpr int RB_U2  = N_N + U_N;
constexpr int RB_I1  = N_N + 2 * U_N;
constexpr int RB_I2  = N_N + 2 * U_N + I_N;

// attention tiling (16-row tiles, 8 warps/block, one tile per warp)
constexpr int NTU   = (2 * U_N) / 16;            // 6250
constexpr int NTI   = (2 * I_N) / 16;            // 12500
constexpr int BLK_U = (NTU + 7) / 8;             // 782
constexpr int BLK_I = (NTI + 7) / 8;             // 1563
constexpr int GRID_ATTN = BLK_U + BLK_I;         // 2345
constexpr int GRID_GCN  = (N_N * 8 + 255) / 256; // 4688 (8 lanes/row, CEIL!)
constexpr int GRID_FUSE = GRID_ATTN + GRID_GCN;

constexpr int GRID_INIT = (N_N * 16) / 256;      // 9375 (init part of initcnt)

// ---------------------------------------------------------------------------
// Scratch (device globals: allocation-free)
// ---------------------------------------------------------------------------
__device__ __align__(256) __half g_ui16_a[N_N * D];   // fp16 gather ping
__device__ __align__(256) __half g_ui16_b[N_N * D];   // fp16 gather pong
__device__ __align__(256) float  g_ui32[N_N * D];     // fp32 final gcn output
__device__ __align__(256) __half g_hu16[U_N * D];
__device__ __align__(256) __half g_hi16[I_N * D];
__device__ __align__(256) float  g_zu[U_N * 2 * D];
__device__ __align__(256) float  g_zi[I_N * 2 * D];
__device__ __align__(256) float  g_wdst[NTOT];
__device__ __align__(256) float  g_wsrc[DOUT_LEN];
__device__ __align__(256) float  g_wsum[4];
__device__ __align__(256) int    g_int[INT_TOT];
__device__ __align__(256) int    g_S[NSCAN + 8];
__device__ __align__(256) int    g_csr[E_TOT];

// ---------------------------------------------------------------------------
// Helpers
// ---------------------------------------------------------------------------
__device__ __forceinline__ float tanh_fast(float x) {
    float y;
    asm("tanh.approx.f32 %0, %1;" : "=f"(y) : "f"(x));
    return y;
}
__device__ __forceinline__ uint32_t pack_bf16(float lo, float hi) {
    uint32_t r;
    asm("cvt.rn.bf16x2.f32 %0, %1, %2;" : "=r"(r) : "f"(hi), "f"(lo));
    return r;
}
__device__ __forceinline__ void mma16816(float c[4], const uint32_t a[4],
                                         uint32_t b0, uint32_t b1) {
    asm volatile(
        "mma.sync.aligned.m16n8k16.row.col.f32.bf16.bf16.f32 "
        "{%0,%1,%2,%3}, {%4,%5,%6,%7}, {%8,%9}, {%0,%1,%2,%3};"
        : "+f"(c[0]), "+f"(c[1]), "+f"(c[2]), "+f"(c[3])
        : "r"(a[0]), "r"(a[1]), "r"(a[2]), "r"(a[3]), "r"(b0), "r"(b1));
}
__device__ __forceinline__ float2 beta_pair(const float* __restrict__ wsum,
                                            int off, float inv_n) {
    float a = wsum[off] * inv_n;
    float b = wsum[off + 1] * inv_n;
    float m = fmaxf(a, b);
    float e0 = expf(a - m), e1 = expf(b - m);
    float inv = 1.f / (e0 + e1);
    return make_float2(e0 * inv, e1 * inv);
}

// 8 fp32 accumulator
struct f8 { float4 a, b; };
// accumulate w * (8 halves loaded as uint4) into f8
__device__ __forceinline__ void acc_h8(f8& acc, float w, const uint4* row, int lane) {
    uint4 v = row[lane];
    float2 f0 = __half22float2(*(const __half2*)&v.x);
    float2 f1 = __half22float2(*(const __half2*)&v.y);
    float2 f2 = __half22float2(*(const __half2*)&v.z);
    float2 f3 = __half22float2(*(const __half2*)&v.w);
    acc.a.x = fmaf(w, f0.x, acc.a.x); acc.a.y = fmaf(w, f0.y, acc.a.y);
    acc.a.z = fmaf(w, f1.x, acc.a.z); acc.a.w = fmaf(w, f1.y, acc.a.w);
    acc.b.x = fmaf(w, f2.x, acc.b.x); acc.b.y = fmaf(w, f2.y, acc.b.y);
    acc.b.z = fmaf(w, f3.x, acc.b.z); acc.b.w = fmaf(w, f3.y, acc.b.w);
}

// ---------------------------------------------------------------------------
// Kernels
// ---------------------------------------------------------------------------
__global__ void zero_i4_k(int4* p, int n4) {
    int t = blockIdx.x * blockDim.x + threadIdx.x;
    if (t < n4) p[t] = make_int4(0, 0, 0, 0);
}

// ---------------------------------------------------------------------------
// FUSED init + degree counting
// ---------------------------------------------------------------------------
struct CntJobs {
    const int* ptr[9];
    int        dego[9];
    int        E[9];
    int        qcum[10];
};

__global__ void initcnt_k(const float4* __restrict__ uf, const float4* __restrict__ itf,
                          CntJobs J) {
    if (blockIdx.x < GRID_INIT) {
        int t = blockIdx.x * blockDim.x + threadIdx.x;   // handles 4 floats
        float4 v;
        __half2* hdst;
        int hidx;
        if (t < U_N * 16) {
            v = uf[t];
            hdst = (__half2*)g_hu16; hidx = 2 * t;
        } else {
            v = itf[t - U_N * 16];
            hdst = (__half2*)g_hi16; hidx = 2 * (t - U_N * 16);
        }
        __half2 h0 = __floats2half2_rn(v.x, v.y);
        __half2 h1 = __floats2half2_rn(v.z, v.w);
        ((__half2*)g_ui16_a)[2 * t]     = h0;
        ((__half2*)g_ui16_a)[2 * t + 1] = h1;
        hdst[hidx]     = h0;
        hdst[hidx + 1] = h1;
        return;
    }
    int t = (blockIdx.x - GRID_INIT) * blockDim.x + threadIdx.x;
    if (t >= J.qcum[9]) return;
    int j = 0;
    #pragma unroll
    for (int k = 1; k < 9; k++) j += (t >= J.qcum[k]);
    int e0 = (t - J.qcum[j]) * 4;
    int E = J.E[j];
    const int* p = J.ptr[j];
    int* base = g_int + J.dego[j];
    #pragma unroll
    for (int i = 0; i < 4; i++) {
        int e = e0 + i;
        if (e < E) atomicAdd(&base[p[e]], 1);
    }
}

// --- scan phase 1 ---
__global__ void scan1_k(const int* __restrict__ deg, int n,
                        int* __restrict__ S, int* __restrict__ part) {
    __shared__ int warpsum[8];
    int base = blockIdx.x * 2048 + threadIdx.x * 8;
    int v[8];
    int s = 0;
    #pragma unroll
    for (int i = 0; i < 8; i++) {
        int x = (base + i < n) ? deg[base + i] : 0;
        v[i] = s; s += x;
    }
    int lane = threadIdx.x & 31, w = threadIdx.x >> 5;
    int ts = s;
    #pragma unroll
    for (int o = 1; o < 32; o <<= 1) {
        int y = __shfl_up_sync(0xffffffffu, ts, o);
        if (lane >= o) ts += y;
    }
    if (lane == 31) warpsum[w] = ts;
    __syncthreads();
    if (w == 0 && lane < 8) {
        int x = warpsum[lane];
        #pragma unroll
        for (int o = 1; o < 8; o <<= 1) {
            int y = __shfl_up_sync(0xffu, x, o);
            if (lane >= o) x += y;
        }
        warpsum[lane] = x;
    }
    __syncthreads();
    int prefix = (w > 0 ? warpsum[w - 1] : 0) + (ts - s);
    #pragma unroll
    for (int i = 0; i < 8; i++)
        if (base + i < n) S[base + i] = prefix + v[i];
    if (threadIdx.x == 0) part[blockIdx.x] = warpsum[7];
}

// --- scan phase 2+3 fused with cursor init + weights ---
__global__ void scan23w_k(int nchunks) {
    __shared__ int sh[256];
    {
        int t = threadIdx.x;
        int x = (t < nchunks) ? g_int[OFF_PART + t] : 0;
        sh[t] = x;
        __syncthreads();
        for (int o = 1; o < 256; o <<= 1) {
            int y = (t >= o) ? sh[t - o] : 0;
            __syncthreads();
            sh[t] += y;
            __syncthreads();
        }
    }
    int psum = (blockIdx.x > 0) ? sh[blockIdx.x - 1] : 0;
    int base = blockIdx.x * 2048 + threadIdx.x * 8;
    #pragma unroll
    for (int i = 0; i < 8; i++) {
        int t = base + i;
        if (t >= NSCAN) break;
        int sv = g_S[t] + psum;
        g_S[t] = sv;
        if (t < NTOT) {
            g_int[OFF_CNT + t] = sv;
            float d = (float)g_int[OFF_DEG + t];
            g_wdst[t] = (t < N_N) ? ((d > 0.f) ? rsqrtf(d) : 0.f)
                                  : rsqrtf(fmaxf(d, 1.f));
        }
        if (t < DOUT_LEN)
            g_wsrc[t] = rsqrtf(fmaxf((float)g_int[OFF_DOUT + t], 1.f));
    }
}

// ---------------------------------------------------------------------------
// Fused CSR fill
// ---------------------------------------------------------------------------
struct FillJobs {
    const int* src[5];
    const int* dst[5];
    int        rb[5];
    int        E[5];
    int        qcum[6];
};

__global__ void fill_all_k(FillJobs J) {
    int t = blockIdx.x * blockDim.x + threadIdx.x;
    if (t >= J.qcum[5]) return;
    int j = 0;
    #pragma unroll
    for (int k = 1; k < 5; k++) j += (t >= J.qcum[k]);
    int e0 = (t - J.qcum[j]) * 4;
    int E = J.E[j];
    const int* src = J.src[j];
    const int* dst = J.dst[j];
    int* cur = g_int + OFF_CNT + J.rb[j];
    #pragma unroll
    for (int i = 0; i < 4; i++) {
        int e = e0 + i;
        if (e < E) {
            int p = atomicAdd(&cur[dst[e]], 1);
            g_csr[p] = src[e];
        }
    }
}

// ---------------------------------------------------------------------------
// fp16 CSR pull body: QUARTER-warp (8 lanes) per row, uint4 (16B) payload.
// 4 rows per warp -> 16 independent gathers in flight per warp.
// ---------------------------------------------------------------------------
__device__ __forceinline__ f8 pull_row16(const int* __restrict__ S,
                                         const int* __restrict__ csr,
                                         const float* __restrict__ wsrc,
                                         const float* __restrict__ wdst,
                                         const uint4* __restrict__ in,  // row stride 8 uint4
                                         int r, int lane) {
    int s = S[r], e = S[r + 1];
    f8 acc;
    acc.a = make_float4(0.f, 0.f, 0.f, 0.f);
    acc.b = make_float4(0.f, 0.f, 0.f, 0.f);
    int j = s;
    for (; j + 4 <= e; j += 4) {
        int c0 = csr[j], c1 = csr[j + 1], c2 = csr[j + 2], c3 = csr[j + 3];
        float w0 = wsrc[c0], w1 = wsrc[c1], w2 = wsrc[c2], w3 = wsrc[c3];
        acc_h8(acc, w0, in + (size_t)c0 * 8, lane);
        acc_h8(acc, w1, in + (size_t)c1 * 8, lane);
        acc_h8(acc, w2, in + (size_t)c2 * 8, lane);
        acc_h8(acc, w3, in + (size_t)c3 * 8, lane);
    }
    for (; j < e; j++) {
        int c = csr[j];
        acc_h8(acc, wsrc[c], in + (size_t)c * 8, lane);
    }
    float wd = wdst[r];
    acc.a.x *= wd; acc.a.y *= wd; acc.a.z *= wd; acc.a.w *= wd;
    acc.b.x *= wd; acc.b.y *= wd; acc.b.z *= wd; acc.b.w *= wd;
    return acc;
}

// ---------------------------------------------------------------------------
// Fused HAN pulls: all 4 metapath graphs (300K rows, 8 lanes/row), fp16 in,
// fp32 z out; also resets wsum for the following attention kernel.
// ---------------------------------------------------------------------------
__global__ void hanpull_k() {
    if (blockIdx.x == 0 && threadIdx.x < 4) g_wsum[threadIdx.x] = 0.f;
    int gid = blockIdx.x * blockDim.x + threadIdx.x;
    int gr = gid >> 3;   // 0 .. 300K
    if (gr >= 2 * U_N + 2 * I_N) return;
    int lane = gid & 7;
    int R = RB_U1 + gr;

    const uint4* in;
    float* out;
    const float* ws;
    int ooff, lr;
    if (gr < U_N)                { in = (const uint4*)g_hu16; out = g_zu; ws = g_wsrc;                 ooff = 0;  lr = gr; }
    else if (gr < 2 * U_N)       { in = (const uint4*)g_hu16; out = g_zu; ws = g_wsrc + U_N;           ooff = 64; lr = gr - U_N; }
    else if (gr < 2 * U_N + I_N) { in = (const uint4*)g_hi16; out = g_zi; ws = g_wsrc + 2 * U_N;       ooff = 0;  lr = gr - 2 * U_N; }
    else                         { in = (const uint4*)g_hi16; out = g_zi; ws = g_wsrc + 2 * U_N + I_N; ooff = 64; lr = gr - 2 * U_N - I_N; }

    f8 o = pull_row16(g_S, g_csr, ws, g_wdst, in, R, lane);
    float* dst = out + (size_t)lr * 128 + ooff + lane * 8;
    *(float4*)dst       = o.a;
    *(float4*)(dst + 4) = o.b;
}

// ---------------------------------------------------------------------------
// FUSED: HAN attention (user+item, tensor cores) co-resident with gcn pull.
// gcn pull: fp16 in, 8 lanes/row; iter0 writes fp16 pong, iter1 fp32 g_ui32.
// ---------------------------------------------------------------------------
constexpr int WT_STRIDE = 72;

__global__ void gcn_attn_k(const uint4* __restrict__ ui_in16,
                           uint4* __restrict__ ui_out16,
                           float* __restrict__ ui_out32, int last,
                           const float* __restrict__ W1u, const float* __restrict__ b1u,
                           const float* __restrict__ w2u,
                           const float* __restrict__ W1i, const float* __restrict__ b1i,
                           const float* __restrict__ w2i) {
    if (blockIdx.x >= GRID_ATTN) {
        // ---- gcn pull path ----
        int gid = (blockIdx.x - GRID_ATTN) * blockDim.x + threadIdx.x;
        int r = gid >> 3;
        if (r < N_N) {
            int lane = gid & 7;
            f8 o = pull_row16(g_S + RB_GCN, g_csr, g_wdst + RB_GCN,
                              g_wdst + RB_GCN, ui_in16, r, lane);
            if (last) {
                float* dst = ui_out32 + (size_t)r * D + lane * 8;
                *(float4*)dst       = o.a;
                *(float4*)(dst + 4) = o.b;
            } else {
                uint4 hv;
                *(__half2*)&hv.x = __floats2half2_rn(o.a.x, o.a.y);
                *(__half2*)&hv.y = __floats2half2_rn(o.a.z, o.a.w);
                *(__half2*)&hv.z = __floats2half2_rn(o.b.x, o.b.y);
                *(__half2*)&hv.w = __floats2half2_rn(o.b.z, o.b.w);
                ui_out16[(size_t)r * 8 + lane] = hv;
            }
        }
        return;
    }

    // ---- attention path (fp32 zu/zi, unchanged) ----
    bool isU = blockIdx.x < BLK_U;
    const float* z  = isU ? g_zu : g_zi;
    const float* W1 = isU ? W1u : W1i;
    const float* b1 = isU ? b1u : b1i;
    const float* w2 = isU ? w2u : w2i;
    int ntiles = isU ? NTU : NTI;
    int bid    = isU ? blockIdx.x : blockIdx.x - BLK_U;
    float* wsp = g_wsum + (isU ? 0 : 2);

    __shared__ __align__(16) __nv_bfloat16 Wt[HID * WT_STRIDE];
    __shared__ float b1s[HID];
    __shared__ float w2s[HID];
    __shared__ float r0s[256], r1s[256];

    for (int i = threadIdx.x; i < D * HID; i += blockDim.x) {
        int k = i >> 7, h = i & 127;
        Wt[h * WT_STRIDE + k] = __float2bfloat16(W1[i]);
    }
    if (threadIdx.x < HID) {
        b1s[threadIdx.x] = b1[threadIdx.x];
        w2s[threadIdx.x] = w2[threadIdx.x];
    }
    __syncthreads();

    int warp = threadIdx.x >> 5;
    int lane = threadIdx.x & 31;
    int g = lane >> 2;
    int tig = lane & 3;
    int tile = bid * 8 + warp;

    float acc0 = 0.f, acc1 = 0.f;

    if (tile < ntiles) {
        const float* zb = z + (size_t)tile * 16 * D;
        uint32_t A[4][4];
        #pragma unroll
        for (int kt = 0; kt < 4; kt++) {
            int k0 = kt * 16 + tig * 2;
            float2 v;
            v = *(const float2*)(zb + g * D + k0);            A[kt][0] = pack_bf16(v.x, v.y);
            v = *(const float2*)(zb + (g + 8) * D + k0);      A[kt][1] = pack_bf16(v.x, v.y);
            v = *(const float2*)(zb + g * D + k0 + 8);        A[kt][2] = pack_bf16(v.x, v.y);
            v = *(const float2*)(zb + (g + 8) * D + k0 + 8);  A[kt][3] = pack_bf16(v.x, v.y);
        }
        float s0 = 0.f, s1 = 0.f;
        #pragma unroll
        for (int nt = 0; nt < 16; nt++) {
            float c[4] = {0.f, 0.f, 0.f, 0.f};
            const __nv_bfloat16* wrow = Wt + (nt * 8 + g) * WT_STRIDE;
            #pragma unroll
            for (int kt = 0; kt < 4; kt++) {
                uint32_t b0 = *(const uint32_t*)(wrow + kt * 16 + tig * 2);
                uint32_t b1v = *(const uint32_t*)(wrow + kt * 16 + tig * 2 + 8);
                mma16816(c, A[kt], b0, b1v);
            }
            int col0 = nt * 8 + tig * 2;
            float bb0 = b1s[col0], bb1 = b1s[col0 + 1];
            float ww0 = w2s[col0], ww1 = w2s[col0 + 1];
            s0 = fmaf(tanh_fast(c[0] + bb0), ww0, s0);
            s0 = fmaf(tanh_fast(c[1] + bb1), ww1, s0);
            s1 = fmaf(tanh_fast(c[2] + bb0), ww0, s1);
            s1 = fmaf(tanh_fast(c[3] + bb1), ww1, s1);
        }
        s0 += __shfl_xor_sync(0xffffffffu, s0, 1);
        s0 += __shfl_xor_sync(0xffffffffu, s0, 2);
        s1 += __shfl_xor_sync(0xffffffffu, s1, 1);
        s1 += __shfl_xor_sync(0xffffffffu, s1, 2);
        if (tig == 0) {
            float v = s0 + s1;
            if (g & 1) acc1 += v; else acc0 += v;
        }
    }

    r0s[threadIdx.x] = acc0;
    r1s[threadIdx.x] = acc1;
    __syncthreads();
    for (int s = blockDim.x >> 1; s > 0; s >>= 1) {
        if (threadIdx.x < s) {
            r0s[threadIdx.x] += r0s[threadIdx.x + s];
            r1s[threadIdx.x] += r1s[threadIdx.x + s];
        }
        __syncthreads();
    }
    if (threadIdx.x == 0) {
        atomicAdd(&wsp[0], r0s[0]);
        atomicAdd(&wsp[1], r1s[0]);
    }
}

// ---------------------------------------------------------------------------
// Fused combine (user + item), beta inline; writes fp16 h (iteration 1 only)
// ---------------------------------------------------------------------------
__global__ void combine_all_k() {
    int t = blockIdx.x * blockDim.x + threadIdx.x;
    if (t >= (U_N + I_N) * 16) return;
    int node = t >> 4;
    int c = t & 15;
    const float4* z;
    __half2* h;
    float2 bb;
    if (node < U_N) {
        z = (const float4*)g_zu; h = (__half2*)g_hu16;
        bb = beta_pair(g_wsum, 0, 1.0f / U_N);
    } else {
        node -= U_N;
        z = (const float4*)g_zi; h = (__half2*)g_hi16;
        bb = beta_pair(g_wsum, 2, 1.0f / I_N);
    }
    float4 z0 = z[node * 32 + c];
    float4 z1 = z[node * 32 + 16 + c];
    float rx = fmaf(bb.x, z0.x, bb.y * z1.x);
    float ry = fmaf(bb.x, z0.y, bb.y * z1.y);
    float rz = fmaf(bb.x, z0.z, bb.y * z1.z);
    float rw = fmaf(bb.x, z0.w, bb.y * z1.w);
    h[node * 32 + c * 2]     = __floats2half2_rn(rx, ry);
    h[node * 32 + c * 2 + 1] = __floats2half2_rn(rz, rw);
}

// epilogue: iter-2 combine fused into the batched gathers; beta inline
__global__ void out_k(const int* __restrict__ uidx, const int* __restrict__ iidx,
                      const int* __restrict__ nidx, float* __restrict__ out) {
    int t = blockIdx.x * blockDim.x + threadIdx.x;
    if (t >= B_N * 16) return;
    int b = t >> 4;
    int c = t & 15;
    const float4* zu4 = (const float4*)g_zu;
    const float4* zi4 = (const float4*)g_zi;
    const float4* ui4 = (const float4*)g_ui32;
    float4* o4 = (float4*)out;
    float2 bU = beta_pair(g_wsum, 0, 1.0f / U_N);
    float2 bI = beta_pair(g_wsum, 2, 1.0f / I_N);

    {
        int u = uidx[b];
        float4 z0 = zu4[u * 32 + c];
        float4 z1 = zu4[u * 32 + 16 + c];
        float4 g = ui4[u * 16 + c];
        float4 r;
        r.x = 0.5f * (fmaf(bU.x, z0.x, bU.y * z1.x) + g.x);
        r.y = 0.5f * (fmaf(bU.x, z0.y, bU.y * z1.y) + g.y);
        r.z = 0.5f * (fmaf(bU.x, z0.z, bU.y * z1.z) + g.z);
        r.w = 0.5f * (fmaf(bU.x, z0.w, bU.y * z1.w) + g.w);
        o4[t] = r;
    }
    {
        int it = iidx[b];
        float4 z0 = zi4[it * 32 + c];
        float4 z1 = zi4[it * 32 + 16 + c];
        float4 g = ui4[(U_N + it) * 16 + c];
        float4 r;
        r.x = 0.5f * (fmaf(bI.x, z0.x, bI.y * z1.x) + g.x);
        r.y = 0.5f * (fmaf(bI.x, z0.y, bI.y * z1.y) + g.y);
        r.z = 0.5f * (fmaf(bI.x, z0.z, bI.y * z1.z) + g.z);
        r.w = 0.5f * (fmaf(bI.x, z0.w, bI.y * z1.w) + g.w);
        o4[B_N * 16 + t] = r;
    }
    {
        int itn = iidx[nidx[b]];
        float4 z0 = zi4[itn * 32 + c];
        float4 z1 = zi4[itn * 32 + 16 + c];
        float4 g = ui4[(U_N + itn) * 16 + c];
        float4 r;
        r.x = 0.5f * (fmaf(bI.x, z0.x, bI.y * z1.x) + g.x);
        r.y = 0.5f * (fmaf(bI.x, z0.y, bI.y * z1.y) + g.y);
        r.z = 0.5f * (fmaf(bI.x, z0.z, bI.y * z1.z) + g.z);
        r.w = 0.5f * (fmaf(bI.x, z0.w, bI.y * z1.w) + g.w);
        o4[2 * B_N * 16 + t] = r;
    }
}

// ---------------------------------------------------------------------------
// Host
// ---------------------------------------------------------------------------
static inline int nblk(long long n) { return (int)((n + 255) / 256); }

extern "C" void kernel_launch(void* const* d_in, const int* in_sizes, int n_in,
                              void* d_out, int out_size) {
    const float* user_feat = (const float*)d_in[0];
    const float* item_feat = (const float*)d_in[1];
    const float* sa_u_W1   = (const float*)d_in[2];
    const float* sa_u_b1   = (const float*)d_in[3];
    const float* sa_u_w2   = (const float*)d_in[4];
    const float* sa_i_W1   = (const float*)d_in[5];
    const float* sa_i_b1   = (const float*)d_in[6];
    const float* sa_i_w2   = (const float*)d_in[7];
    const int*   ui_e      = (const int*)d_in[8];
    const int*   ue1       = (const int*)d_in[9];
    const int*   ue2       = (const int*)d_in[10];
    const int*   ie1       = (const int*)d_in[11];
    const int*   ie2       = (const int*)d_in[12];
    const int*   uidx      = (const int*)d_in[13];
    const int*   iidx      = (const int*)d_in[14];
    const int*   nidx      = (const int*)d_in[15];

    const int Eui = in_sizes[8]  / 2;   // 2,000,000
    const int Eu  = in_sizes[9]  / 2;   //   500,000
    const int Ei  = in_sizes[11] / 2;   // 1,000,000

    __half *ui16_a, *ui16_b;
    float* ui32;
    int *ibuf, *S;
    cudaGetSymbolAddress((void**)&ui16_a, g_ui16_a);
    cudaGetSymbolAddress((void**)&ui16_b, g_ui16_b);
    cudaGetSymbolAddress((void**)&ui32,   g_ui32);
    cudaGetSymbolAddress((void**)&ibuf,   g_int);
    cudaGetSymbolAddress((void**)&S,      g_S);

    const int T = 256;

    // ---- zero int scratch ----
    zero_i4_k<<<nblk(INT_TOT / 4), T>>>((int4*)ibuf, INT_TOT / 4);

    // ---- fused init + degree counting ----
    CntJobs cj;
    const int* cp[9]  = {ui_e, ue1 + Eu, ue2 + Eu, ie1 + Ei, ie2 + Ei,
                         ue1, ue2, ie1, ie2};
    const int  ce[9]  = {Eui, Eu, Eu, Ei, Ei, Eu, Eu, Ei, Ei};
    const int  cd[9]  = {OFF_DEG + RB_GCN, OFF_DEG + RB_U1, OFF_DEG + RB_U2,
                         OFF_DEG + RB_I1, OFF_DEG + RB_I2,
                         OFF_DOUT + 0, OFF_DOUT + U_N,
                         OFF_DOUT + 2 * U_N, OFF_DOUT + 2 * U_N + I_N};
    {
        int acc = 0;
        for (int k = 0; k < 9; k++) {
            cj.ptr[k] = cp[k]; cj.dego[k] = cd[k]; cj.E[k] = ce[k];
            cj.qcum[k] = acc; acc += (ce[k] + 3) / 4;
        }
        cj.qcum[9] = acc;
        initcnt_k<<<GRID_INIT + nblk(acc), T>>>((const float4*)user_feat,
                                                (const float4*)item_feat, cj);
    }

    // ---- scan -> CSR row offsets; fused cursor init + weights ----
    const int nchunks = (NSCAN + 2047) / 2048;  // 220
    scan1_k<<<nchunks, T>>>(ibuf + OFF_DEG, NSCAN, S, ibuf + OFF_PART);
    scan23w_k<<<nchunks, 256>>>(nchunks);

    // ---- fused CSR fill ----
    FillJobs fj;
    const int* fs[5] = {ui_e + Eui, ue1, ue2, ie1, ie2};
    const int* fd[5] = {ui_e, ue1 + Eu, ue2 + Eu, ie1 + Ei, ie2 + Ei};
    const int  fe[5] = {Eui, Eu, Eu, Ei, Ei};
    const int  fb[5] = {RB_GCN, RB_U1, RB_U2, RB_I1, RB_I2};
    {
        int acc = 0;
        for (int k = 0; k < 5; k++) {
            fj.src[k] = fs[k]; fj.dst[k] = fd[k]; fj.rb[k] = fb[k]; fj.E[k] = fe[k];
            fj.qcum[k] = acc; acc += (fe[k] + 3) / 4;
        }
        fj.qcum[5] = acc;
        fill_all_k<<<nblk(acc), T>>>(fj);
    }

    // ---- 2 propagation iterations ----
    // iter 0: gcn gathers ui16_a -> ui16_b (fp16); combine writes fp16 h
    hanpull_k<<<nblk((long long)(2 * U_N + 2 * I_N) * 8), T>>>();
    gcn_attn_k<<<GRID_FUSE, 256>>>((const uint4*)ui16_a, (uint4*)ui16_b,
                                   nullptr, 0,
                                   sa_u_W1, sa_u_b1, sa_u_w2,
                                   sa_i_W1, sa_i_b1, sa_i_w2);
    combine_all_k<<<nblk((long long)(U_N + I_N) * 16), T>>>();

    // iter 1: gcn gathers ui16_b -> ui32 (fp32 epilogue source)
    hanpull_k<<<nblk((long long)(2 * U_N + 2 * I_N) * 8), T>>>();
    gcn_attn_k<<<GRID_FUSE, 256>>>((const uint4*)ui16_b, nullptr,
                                   ui32, 1,
                                   sa_u_W1, sa_u_b1, sa_u_w2,
                                   sa_i_W1, sa_i_b1, sa_i_w2);

    // ---- epilogue ----
    out_k<<<nblk((long long)B_N * 16), T>>>(uidx, iidx, nidx, (float*)d_out);
}